// round 10
// baseline (speedup 1.0000x reference)
#include <cuda_runtime.h>
#include <cuda_bf16.h>
#include <cuda_fp16.h>
#include <math.h>
#include <stdint.h>

#define B_ 2
#define S_ 2048
#define D_ 1024
#define H_ 16
#define HD_ 64
#define M_ 4096

// ---------------- scratch (__device__ globals; allocation-free rule) -------
__device__ __nv_bfloat16 g_xhi[M_ * D_];
__device__ __nv_bfloat16 g_xlo[M_ * D_];
__device__ __nv_bfloat16 g_ahi[M_ * D_];
__device__ __nv_bfloat16 g_alo[M_ * D_];
__device__ __nv_bfloat16 g_wthi[4 * D_ * D_];   // W^T as [n][k], bf16 hi
__device__ __nv_bfloat16 g_wtlo[4 * D_ * D_];   // bf16 lo
__device__ __nv_bfloat16 g_qh[M_ * D_];         // [B,H,S,HD] layouts
__device__ __nv_bfloat16 g_ql[M_ * D_];
__device__ __nv_bfloat16 g_kh[M_ * D_];
__device__ __nv_bfloat16 g_kl[M_ * D_];
__device__ __half        g_vh[M_ * D_];         // V in fp16 hi/lo
__device__ __half        g_vl[M_ * D_];

// ---------------- helpers ---------------------------------------------------
__device__ __forceinline__ uint32_t smem_u32(const void* p) {
    uint32_t a;
    asm("{ .reg .u64 t; cvta.to.shared.u64 t, %1; cvt.u32.u64 %0, t; }"
        : "=r"(a) : "l"(p));
    return a;
}
__device__ __forceinline__ void cp16(uint32_t dst, const void* src) {
    asm volatile("cp.async.cg.shared.global [%0], [%1], 16;" :: "r"(dst), "l"(src));
}
__device__ __forceinline__ void cp_commit() {
    asm volatile("cp.async.commit_group;" ::: "memory");
}
__device__ __forceinline__ void cp_wait1() {
    asm volatile("cp.async.wait_group 1;" ::: "memory");
}
__device__ __forceinline__ void cp_wait0() {
    asm volatile("cp.async.wait_group 0;" ::: "memory");
}
__device__ __forceinline__ void ldsm4(uint32_t* r, uint32_t addr) {
    asm volatile("ldmatrix.sync.aligned.m8n8.x4.shared.b16 {%0,%1,%2,%3}, [%4];"
                 : "=r"(r[0]), "=r"(r[1]), "=r"(r[2]), "=r"(r[3]) : "r"(addr));
}
__device__ __forceinline__ void ldsm4t(uint32_t* r, uint32_t addr) {
    asm volatile("ldmatrix.sync.aligned.m8n8.x4.trans.shared.b16 {%0,%1,%2,%3}, [%4];"
                 : "=r"(r[0]), "=r"(r[1]), "=r"(r[2]), "=r"(r[3]) : "r"(addr));
}
__device__ __forceinline__ void mma16816(float* c, const uint32_t* a,
                                         uint32_t b0, uint32_t b1) {
    asm volatile(
        "mma.sync.aligned.m16n8k16.row.col.f32.bf16.bf16.f32 "
        "{%0,%1,%2,%3}, {%4,%5,%6,%7}, {%8,%9}, {%0,%1,%2,%3};"
        : "+f"(c[0]), "+f"(c[1]), "+f"(c[2]), "+f"(c[3])
        : "r"(a[0]), "r"(a[1]), "r"(a[2]), "r"(a[3]), "r"(b0), "r"(b1));
}
__device__ __forceinline__ void mma16816h(float* c, const uint32_t* a,
                                          uint32_t b0, uint32_t b1) {
    asm volatile(
        "mma.sync.aligned.m16n8k16.row.col.f32.f16.f16.f32 "
        "{%0,%1,%2,%3}, {%4,%5,%6,%7}, {%8,%9}, {%0,%1,%2,%3};"
        : "+f"(c[0]), "+f"(c[1]), "+f"(c[2]), "+f"(c[3])
        : "r"(a[0]), "r"(a[1]), "r"(a[2]), "r"(a[3]), "r"(b0), "r"(b1));
}
__device__ __forceinline__ float ex2f(float x) {
    float r;
    asm("ex2.approx.ftz.f32 %0, %1;" : "=f"(r) : "f"(x));
    return r;
}
// XOR swizzle for 128B rows (flash): 8 x 16B units
#define SWF(r, c) ((uint32_t)((r) * 128 + ((((c) ^ ((r) & 7))) << 4)))

__device__ __forceinline__ uint32_t pack_bf16_hi(float x, float y,
                                                 float& rx, float& ry) {
    __nv_bfloat16 hx = __float2bfloat16_rn(x);
    __nv_bfloat16 hy = __float2bfloat16_rn(y);
    rx = x - __bfloat162float(hx);
    ry = y - __bfloat162float(hy);
    __nv_bfloat162 p; p.x = hx; p.y = hy;
    return *(uint32_t*)&p;
}
__device__ __forceinline__ uint32_t pack_bf16(float x, float y) {
    __nv_bfloat162 p;
    p.x = __float2bfloat16_rn(x);
    p.y = __float2bfloat16_rn(y);
    return *(uint32_t*)&p;
}
__device__ __forceinline__ uint32_t pack_f16_hi(float x, float y,
                                                float& rx, float& ry) {
    __half hx = __float2half_rn(x);
    __half hy = __float2half_rn(y);
    rx = x - __half2float(hx);
    ry = y - __half2float(hy);
    __half2 p; p.x = hx; p.y = hy;
    return *(uint32_t*)&p;
}
__device__ __forceinline__ uint32_t pack_f16(float x, float y) {
    __half2 p = __floats2half2_rn(x, y);
    return *(uint32_t*)&p;
}

// ---------------------------------------------------------------------------
// Conversion kernels
// ---------------------------------------------------------------------------
__global__ void split_kernel(const float* __restrict__ src,
                             __nv_bfloat16* __restrict__ hi,
                             __nv_bfloat16* __restrict__ lo, int n)
{
    const int base = blockIdx.x * 4096 + threadIdx.x * 4;
#pragma unroll
    for (int p = 0; p < 4; p++) {
        const int i = base + p * 1024;
        if (i >= n) return;
        float4 v = *(const float4*)(src + i);
        float lx, ly, lz, lw;
        uint32_t h0 = pack_bf16_hi(v.x, v.y, lx, ly);
        uint32_t h1 = pack_bf16_hi(v.z, v.w, lz, lw);
        *(uint32_t*)(hi + i)     = h0;
        *(uint32_t*)(hi + i + 2) = h1;
        *(uint32_t*)(lo + i)     = pack_bf16(lx, ly);
        *(uint32_t*)(lo + i + 2) = pack_bf16(lz, lw);
    }
}

// W [k][n] fp32 -> W^T [n][k] bf16 hi/lo. Tile: 32 k x 64 n. 256 threads.
__global__ void transW_kernel(const float* __restrict__ W0, const float* __restrict__ W1,
                              const float* __restrict__ W2, const float* __restrict__ W3,
                              __nv_bfloat16* __restrict__ ohi, __nv_bfloat16* __restrict__ olo)
{
    __shared__ float t[32][65];
    const int z = blockIdx.z;
    const float* W = (z == 0) ? W0 : (z == 1) ? W1 : (z == 2) ? W2 : W3;
    const int n0 = blockIdx.x * 64, k0 = blockIdx.y * 32;
    const int tid = threadIdx.x;
#pragma unroll
    for (int p = 0; p < 8; p++) {
        const int lin = tid + p * 256;
        const int r = lin >> 6, c = lin & 63;
        t[r][c] = W[(size_t)(k0 + r) * D_ + n0 + c];
    }
    __syncthreads();
    __nv_bfloat16* Oh = ohi + (size_t)z * D_ * D_;
    __nv_bfloat16* Ol = olo + (size_t)z * D_ * D_;
    const int n = n0 + (tid >> 2);
    const int kb = (tid & 3) * 8;
    uint32_t hv[4], lv[4];
#pragma unroll
    for (int j = 0; j < 4; j++) {
        const float vx = t[kb + 2 * j][tid >> 2];
        const float vy = t[kb + 2 * j + 1][tid >> 2];
        float lx, ly;
        hv[j] = pack_bf16_hi(vx, vy, lx, ly);
        lv[j] = pack_bf16(lx, ly);
    }
    *(uint4*)&Oh[(size_t)n * D_ + k0 + kb] = *(uint4*)hv;
    *(uint4*)&Ol[(size_t)n * D_ + k0 + kb] = *(uint4*)lv;
}

// ---------------------------------------------------------------------------
// mma.sync bf16 GEMM (hi/lo split, 3 terms): C = A @ Wt^T + bias
// CTA 128x128, 256 threads (8 warps 4x2), BK=32.
// 64B smem rows, XOR swizzle, 3-stage distance-2 pipeline, ONE barrier/chunk.
// ---------------------------------------------------------------------------
#define GBUF (128 * 64)
#define GSTAGE (4 * GBUF)
#define GEMM_SMEM (3 * GSTAGE)
#define LOG2E 1.4426950408889634f

template <int SCATTER>
__global__ __launch_bounds__(256, 2) void gemm_mma_kernel(
    const __nv_bfloat16* __restrict__ Ah, const __nv_bfloat16* __restrict__ Al,
    const __nv_bfloat16* __restrict__ Wth, const __nv_bfloat16* __restrict__ Wtl,
    const float* __restrict__ b0p, const float* __restrict__ b1p,
    const float* __restrict__ b2p,
    float* __restrict__ fo,
    __nv_bfloat16* __restrict__ oh0, __nv_bfloat16* __restrict__ ol0,
    __nv_bfloat16* __restrict__ oh1, __nv_bfloat16* __restrict__ ol1,
    __half* __restrict__ oh2, __half* __restrict__ ol2)
{
    extern __shared__ __align__(16) char smem[];
    const uint32_t sbase = smem_u32(smem);
    const int tid  = threadIdx.x;
    const int wid  = tid >> 5;
    const int lane = tid & 31;
    const int wm   = wid & 3;
    const int wn   = wid >> 2;
    const int n0 = blockIdx.x * 128;
    const int m0 = blockIdx.y * 128;
    const int z  = blockIdx.z;

    const __nv_bfloat16* Bh = Wth + (size_t)z * D_ * D_;
    const __nv_bfloat16* Bl = Wtl + (size_t)z * D_ * D_;
    const float* bias = (z == 0) ? b0p : (z == 1) ? b1p : b2p;
    __nv_bfloat16* Ohp = (z == 0) ? oh0 : oh1;
    __nv_bfloat16* Olp = (z == 0) ? ol0 : ol1;
    const float scl = (SCATTER && z == 0) ? (0.125f * LOG2E) : 1.0f;

    float c[2][8][4];
#pragma unroll
    for (int i = 0; i < 2; i++)
#pragma unroll
        for (int j = 0; j < 8; j++)
#pragma unroll
            for (int q = 0; q < 4; q++) c[i][j][q] = 0.0f;

    const int u0 = tid * 2;
    auto load_chunk = [&](int stage, int kc) {
        const uint32_t sb = sbase + stage * GSTAGE;
#pragma unroll
        for (int u = 0; u < 2; u++) {
            const int idx = u0 + u;
            const int row = idx >> 2;
            const int c4  = idx & 3;
            const uint32_t off = (uint32_t)(row * 64 + ((c4 ^ ((row >> 1) & 3)) << 4));
            const size_t gA = (size_t)(m0 + row) * D_ + kc * 32 + c4 * 8;
            const size_t gB = (size_t)(n0 + row) * D_ + kc * 32 + c4 * 8;
            cp16(sb +            off, Ah + gA);
            cp16(sb + 1 * GBUF + off, Al + gA);
            cp16(sb + 2 * GBUF + off, Bh + gB);
            cp16(sb + 3 * GBUF + off, Bl + gB);
        }
        cp_commit();
    };

    const int a_rowb = wm * 32 + (lane & 15);
    const uint32_t a_mask = (uint32_t)(((lane & 15) >> 1) & 3);
    const uint32_t a_cu   = (uint32_t)(lane >> 4);
    const int b_rowb = wn * 64 + ((lane >> 4) & 1) * 8 + (lane & 7);
    const uint32_t b_mask = (uint32_t)(((lane & 7) >> 1) & 3);
    const uint32_t b_cu   = (uint32_t)((lane >> 3) & 1);

    const int NCHUNK = D_ / 32;   // 32
    load_chunk(0, 0);
    load_chunk(1, 1);

    for (int i = 0; i < NCHUNK; i++) {
        if (i + 1 < NCHUNK) cp_wait1(); else cp_wait0();
        __syncthreads();
        if (i + 2 < NCHUNK) load_chunk((i + 2) % 3, i + 2);

        const uint32_t stg = sbase + (i % 3) * GSTAGE;
        const uint32_t Abh = stg,             Abl = stg + 1u * GBUF;
        const uint32_t Bbh = stg + 2u * GBUF, Bbl = stg + 3u * GBUF;

#pragma unroll
        for (int kkb = 0; kkb < 2; kkb++) {
            const uint32_t acsw = (((uint32_t)(kkb * 2) + a_cu) ^ a_mask) << 4;
            const uint32_t bcsw = (((uint32_t)(kkb * 2) + b_cu) ^ b_mask) << 4;
            uint32_t ah[2][4], al[2][4];
            ldsm4(ah[0], Abh + (uint32_t)(a_rowb) * 64 + acsw);
            ldsm4(ah[1], Abh + (uint32_t)(a_rowb + 16) * 64 + acsw);
            ldsm4(al[0], Abl + (uint32_t)(a_rowb) * 64 + acsw);
            ldsm4(al[1], Abl + (uint32_t)(a_rowb + 16) * 64 + acsw);
#pragma unroll
            for (int half = 0; half < 2; half++) {
                uint32_t bh4[2][4], bl4[2][4];
#pragma unroll
                for (int p = 0; p < 2; p++) {
                    const int np = half * 2 + p;
                    ldsm4(bh4[p], Bbh + (uint32_t)(b_rowb + np * 16) * 64 + bcsw);
                    ldsm4(bl4[p], Bbl + (uint32_t)(b_rowb + np * 16) * 64 + bcsw);
                }
#pragma unroll
                for (int mt = 0; mt < 2; mt++)
#pragma unroll
                    for (int q = 0; q < 4; q++) {
                        const int nt = half * 4 + q;
                        const uint32_t b0h = bh4[q >> 1][(q & 1) * 2];
                        const uint32_t b1h = bh4[q >> 1][(q & 1) * 2 + 1];
                        const uint32_t b0l = bl4[q >> 1][(q & 1) * 2];
                        const uint32_t b1l = bl4[q >> 1][(q & 1) * 2 + 1];
                        float* cc = c[mt][nt];
                        mma16816(cc, ah[mt], b0h, b1h);
                        mma16816(cc, ah[mt], b0l, b1l);
                        mma16816(cc, al[mt], b0h, b1h);
                    }
            }
        }
    }

    const int nb = n0 + wn * 64;
#pragma unroll
    for (int mt = 0; mt < 2; mt++) {
        const int r0 = m0 + wm * 32 + mt * 16 + (lane >> 2);
#pragma unroll
        for (int nt = 0; nt < 8; nt++) {
            const int ng = nb + nt * 8 + (lane & 3) * 2;
            const float bx = bias[ng], by = bias[ng + 1];
            float v0x = (c[mt][nt][0] + bx) * scl, v0y = (c[mt][nt][1] + by) * scl;
            float v1x = (c[mt][nt][2] + bx) * scl, v1y = (c[mt][nt][3] + by) * scl;
            if (SCATTER) {
                const int h = ng >> 6;
                const int dd = ng & 63;
                const int bb0 = r0 >> 11, sI0 = r0 & (S_ - 1);
                const int r1 = r0 + 8;
                const int bb1 = r1 >> 11, sI1 = r1 & (S_ - 1);
                const size_t o0i = ((size_t)(bb0 * H_ + h) * S_ + sI0) * HD_ + dd;
                const size_t o1i = ((size_t)(bb1 * H_ + h) * S_ + sI1) * HD_ + dd;
                float l0x, l0y, l1x, l1y;
                if (z == 2) {
                    *(uint32_t*)&oh2[o0i] = pack_f16_hi(v0x, v0y, l0x, l0y);
                    *(uint32_t*)&ol2[o0i] = pack_f16(l0x, l0y);
                    *(uint32_t*)&oh2[o1i] = pack_f16_hi(v1x, v1y, l1x, l1y);
                    *(uint32_t*)&ol2[o1i] = pack_f16(l1x, l1y);
                } else {
                    *(uint32_t*)&Ohp[o0i] = pack_bf16_hi(v0x, v0y, l0x, l0y);
                    *(uint32_t*)&Olp[o0i] = pack_bf16(l0x, l0y);
                    *(uint32_t*)&Ohp[o1i] = pack_bf16_hi(v1x, v1y, l1x, l1y);
                    *(uint32_t*)&Olp[o1i] = pack_bf16(l1x, l1y);
                }
            } else {
                *(float2*)&fo[(size_t)r0 * D_ + ng] = make_float2(v0x, v0y);
                *(float2*)&fo[(size_t)(r0 + 8) * D_ + ng] = make_float2(v1x, v1y);
            }
        }
    }
}

// ---------------------------------------------------------------------------
// Tensor-core flash attention (log2 softmax).
// QK^T: 3-term bf16 hi/lo. PV: 2-term, P single fp16 x V fp16 hi/lo.
// Key blocks of 32, 64KB smem -> 3 CTAs/SM.
// ---------------------------------------------------------------------------
#define FL_QBUF 16384                  // 128 rows x 128B
#define FL_KVBUF 4096                  // 32 rows x 128B
#define FL_KVST (4 * FL_KVBUF)         // Kh,Kl,Vh,Vl = 16384
#define FL_SMEM (2 * FL_QBUF + 2 * FL_KVST)   // 65536

__global__ __launch_bounds__(256, 3) void flash_tc_kernel(
    const __nv_bfloat16* __restrict__ Qh, const __nv_bfloat16* __restrict__ Ql,
    const __nv_bfloat16* __restrict__ Kh, const __nv_bfloat16* __restrict__ Kl,
    const __half* __restrict__ Vh, const __half* __restrict__ Vl,
    __nv_bfloat16* __restrict__ Oh, __nv_bfloat16* __restrict__ Ol)
{
    extern __shared__ __align__(16) char smem[];
    const uint32_t base = smem_u32(smem);
    const int tid = threadIdx.x, wid = tid >> 5, lane = tid & 31;
    const int q0 = blockIdx.x * 128;
    const int bh = blockIdx.y;
    const size_t hb = (size_t)bh * S_ * HD_;

#pragma unroll
    for (int u = 0; u < 8; u++) {
        const int idx = tid + u * 256;
        const int bsel = idx >> 10;
        const int r = (idx >> 3) & 127;
        const int c = idx & 7;
        const __nv_bfloat16* src = (bsel ? Ql : Qh) + hb + (size_t)(q0 + r) * HD_ + c * 8;
        cp16(base + bsel * FL_QBUF + SWF(r, c), src);
    }
    cp_commit();

    auto loadkv = [&](int st, int kb) {
        const uint32_t sb = base + 2 * FL_QBUF + st * FL_KVST;
#pragma unroll
        for (int u = 0; u < 4; u++) {
            const int idx = tid + u * 256;   // 0..1023
            const int b4 = idx >> 8;
            const int r = (idx >> 3) & 31;
            const int c = idx & 7;
            const void* g;
            if (b4 == 0)      g = Kh + hb + (size_t)(kb * 32 + r) * HD_ + c * 8;
            else if (b4 == 1) g = Kl + hb + (size_t)(kb * 32 + r) * HD_ + c * 8;
            else if (b4 == 2) g = Vh + hb + (size_t)(kb * 32 + r) * HD_ + c * 8;
            else              g = Vl + hb + (size_t)(kb * 32 + r) * HD_ + c * 8;
            cp16(sb + b4 * FL_KVBUF + SWF(r, c), g);
        }
        cp_commit();
    };
    loadkv(0, 0);
    loadkv(1, 1);

    float o[8][4];
#pragma unroll
    for (int nt = 0; nt < 8; nt++)
#pragma unroll
        for (int q = 0; q < 4; q++) o[nt][q] = 0.0f;
    float m0r = -1e30f, m1r = -1e30f, l0 = 0.0f, l1 = 0.0f;

    const int a_row = wid * 16 + (lane & 7) + ((lane >> 3) & 1) * 8;
    const int a_c   = lane >> 4;
    const int k_row = ((lane >> 4) & 1) * 8 + (lane & 7);
    const int k_c   = (lane >> 3) & 1;
    const int v_row = ((lane >> 3) & 1) * 8 + (lane & 7);
    const int v_c   = lane >> 4;

    const int NB = S_ / 32;   // 64
    for (int kb = 0; kb < NB; kb++) {
        if (kb < NB - 1) cp_wait1(); else cp_wait0();
        __syncthreads();
        const uint32_t stg = base + 2 * FL_QBUF + (kb & 1) * FL_KVST;

        float s[4][4];
#pragma unroll
        for (int nt = 0; nt < 4; nt++)
#pragma unroll
            for (int q = 0; q < 4; q++) s[nt][q] = 0.0f;

#pragma unroll
        for (int ks = 0; ks < 4; ks++) {
            uint32_t ah[4], al[4];
            ldsm4(ah, base +           SWF(a_row, 2 * ks + a_c));
            ldsm4(al, base + FL_QBUF + SWF(a_row, 2 * ks + a_c));
#pragma unroll
            for (int np = 0; np < 2; np++) {
                uint32_t bh4[4], bl4[4];
                ldsm4(bh4, stg +             SWF(np * 16 + k_row, 2 * ks + k_c));
                ldsm4(bl4, stg + FL_KVBUF +  SWF(np * 16 + k_row, 2 * ks + k_c));
#pragma unroll
                for (int hh = 0; hh < 2; hh++) {
                    float* sc = s[2 * np + hh];
                    mma16816(sc, ah, bh4[2 * hh], bh4[2 * hh + 1]);
                    mma16816(sc, ah, bl4[2 * hh], bl4[2 * hh + 1]);
                    mma16816(sc, al, bh4[2 * hh], bh4[2 * hh + 1]);
                }
            }
        }

        float mx0 = -1e30f, mx1 = -1e30f;
#pragma unroll
        for (int nt = 0; nt < 4; nt++) {
            mx0 = fmaxf(mx0, fmaxf(s[nt][0], s[nt][1]));
            mx1 = fmaxf(mx1, fmaxf(s[nt][2], s[nt][3]));
        }
        mx0 = fmaxf(mx0, __shfl_xor_sync(0xffffffffu, mx0, 1));
        mx0 = fmaxf(mx0, __shfl_xor_sync(0xffffffffu, mx0, 2));
        mx1 = fmaxf(mx1, __shfl_xor_sync(0xffffffffu, mx1, 1));
        mx1 = fmaxf(mx1, __shfl_xor_sync(0xffffffffu, mx1, 2));
        const float mn0 = fmaxf(m0r, mx0);
        const float mn1 = fmaxf(m1r, mx1);
        const float al0 = ex2f(m0r - mn0);
        const float al1 = ex2f(m1r - mn1);
        m0r = mn0; m1r = mn1;

        float sum0 = 0.0f, sum1 = 0.0f;
#pragma unroll
        for (int nt = 0; nt < 4; nt++) {
            s[nt][0] = ex2f(s[nt][0] - mn0);
            s[nt][1] = ex2f(s[nt][1] - mn0);
            s[nt][2] = ex2f(s[nt][2] - mn1);
            s[nt][3] = ex2f(s[nt][3] - mn1);
            sum0 += s[nt][0] + s[nt][1];
            sum1 += s[nt][2] + s[nt][3];
        }
        sum0 += __shfl_xor_sync(0xffffffffu, sum0, 1);
        sum0 += __shfl_xor_sync(0xffffffffu, sum0, 2);
        sum1 += __shfl_xor_sync(0xffffffffu, sum1, 1);
        sum1 += __shfl_xor_sync(0xffffffffu, sum1, 2);
        l0 = l0 * al0 + sum0;
        l1 = l1 * al1 + sum1;
#pragma unroll
        for (int nt = 0; nt < 8; nt++) {
            o[nt][0] *= al0; o[nt][1] *= al0;
            o[nt][2] *= al1; o[nt][3] *= al1;
        }

        // pack P as single fp16 fragments
        uint32_t ap[2][4];
#pragma unroll
        for (int kc = 0; kc < 2; kc++) {
            ap[kc][0] = pack_f16(s[2 * kc][0],     s[2 * kc][1]);
            ap[kc][1] = pack_f16(s[2 * kc][2],     s[2 * kc][3]);
            ap[kc][2] = pack_f16(s[2 * kc + 1][0], s[2 * kc + 1][1]);
            ap[kc][3] = pack_f16(s[2 * kc + 1][2], s[2 * kc + 1][3]);
        }

        // O += P V  (2 terms: P x Vh + P x Vl, fp16 mma)
        const uint32_t vhb = stg + 2 * FL_KVBUF, vlb = stg + 3 * FL_KVBUF;
#pragma unroll
        for (int dp = 0; dp < 4; dp++) {
#pragma unroll
            for (int kc = 0; kc < 2; kc++) {
                uint32_t vh4[4], vl4[4];
                ldsm4t(vh4, vhb + SWF(kc * 16 + v_row, 2 * dp + v_c));
                ldsm4t(vl4, vlb + SWF(kc * 16 + v_row, 2 * dp + v_c));
                mma16816h(o[2 * dp],     ap[kc], vh4[0], vh4[1]);
                mma16816h(o[2 * dp],     ap[kc], vl4[0], vl4[1]);
                mma16816h(o[2 * dp + 1], ap[kc], vh4[2], vh4[3]);
                mma16816h(o[2 * dp + 1], ap[kc], vl4[2], vl4[3]);
            }
        }
        __syncthreads();
        if (kb + 2 < NB) loadkv(kb & 1, kb + 2);
    }

    const float inv0 = 1.0f / l0, inv1 = 1.0f / l1;
    const int h = bh & (H_ - 1);
    const int bb = bh >> 4;
    const int r0 = q0 + wid * 16 + (lane >> 2);
    const int r1 = r0 + 8;
#pragma unroll
    for (int nt = 0; nt < 8; nt++) {
        const int gd = h * 64 + nt * 8 + (lane & 3) * 2;
        const size_t i0 = ((size_t)bb * S_ + r0) * D_ + gd;
        const size_t i1 = ((size_t)bb * S_ + r1) * D_ + gd;
        float lx, ly;
        *(uint32_t*)&Oh[i0] = pack_bf16_hi(o[nt][0] * inv0, o[nt][1] * inv0, lx, ly);
        *(uint32_t*)&Ol[i0] = pack_bf16(lx, ly);
        *(uint32_t*)&Oh[i1] = pack_bf16_hi(o[nt][2] * inv1, o[nt][3] * inv1, lx, ly);
        *(uint32_t*)&Ol[i1] = pack_bf16(lx, ly);
    }
}

// ---------------------------------------------------------------------------

extern "C" void kernel_launch(void* const* d_in, const int* in_sizes, int n_in,
                              void* d_out, int out_size)
{
    (void)in_sizes; (void)n_in; (void)out_size;
    const float* x  = (const float*)d_in[0];
    const float* Wq = (const float*)d_in[1];
    const float* bq = (const float*)d_in[2];
    const float* Wk = (const float*)d_in[3];
    const float* bk = (const float*)d_in[4];
    const float* Wv = (const float*)d_in[5];
    const float* bv = (const float*)d_in[6];
    const float* Wo = (const float*)d_in[7];
    const float* bo = (const float*)d_in[8];
    float* out = (float*)d_out;

    __nv_bfloat16 *xhi, *xlo, *ahi, *alo, *wthi, *wtlo;
    __nv_bfloat16 *qh, *ql, *kh, *kl;
    __half *vh, *vl;
    cudaGetSymbolAddress((void**)&xhi,  g_xhi);
    cudaGetSymbolAddress((void**)&xlo,  g_xlo);
    cudaGetSymbolAddress((void**)&ahi,  g_ahi);
    cudaGetSymbolAddress((void**)&alo,  g_alo);
    cudaGetSymbolAddress((void**)&wthi, g_wthi);
    cudaGetSymbolAddress((void**)&wtlo, g_wtlo);
    cudaGetSymbolAddress((void**)&qh,   g_qh);
    cudaGetSymbolAddress((void**)&ql,   g_ql);
    cudaGetSymbolAddress((void**)&kh,   g_kh);
    cudaGetSymbolAddress((void**)&kl,   g_kl);
    cudaGetSymbolAddress((void**)&vh,   g_vh);
    cudaGetSymbolAddress((void**)&vl,   g_vl);

    cudaFuncSetAttribute(gemm_mma_kernel<1>,
        cudaFuncAttributeMaxDynamicSharedMemorySize, GEMM_SMEM);
    cudaFuncSetAttribute(gemm_mma_kernel<0>,
        cudaFuncAttributeMaxDynamicSharedMemorySize, GEMM_SMEM);
    cudaFuncSetAttribute(flash_tc_kernel,
        cudaFuncAttributeMaxDynamicSharedMemorySize, FL_SMEM);

    const int NEL = M_ * D_;
    split_kernel<<<NEL / 4096, 256>>>(x, xhi, xlo, NEL);
    transW_kernel<<<dim3(16, 32, 4), 256>>>(Wq, Wk, Wv, Wo, wthi, wtlo);

    gemm_mma_kernel<1><<<dim3(8, 32, 3), 256, GEMM_SMEM>>>(
        xhi, xlo, wthi, wtlo, bq, bk, bv,
        nullptr, qh, ql, kh, kl, vh, vl);

    flash_tc_kernel<<<dim3(S_ / 128, B_ * H_), 256, FL_SMEM>>>(
        qh, ql, kh, kl, vh, vl, ahi, alo);

    gemm_mma_kernel<0><<<dim3(8, 32, 1), 256, GEMM_SMEM>>>(
        ahi, alo, wthi + (size_t)3 * D_ * D_, wtlo + (size_t)3 * D_ * D_,
        bo, bo, bo, out, nullptr, nullptr, nullptr, nullptr, nullptr, nullptr);
}

// round 11
// speedup vs baseline: 1.2766x; 1.2766x over previous
#include <cuda_runtime.h>
#include <cuda_bf16.h>
#include <cuda_fp16.h>
#include <math.h>
#include <stdint.h>

#define B_ 2
#define S_ 2048
#define D_ 1024
#define H_ 16
#define HD_ 64
#define M_ 4096

// ---------------- scratch (__device__ globals; allocation-free rule) -------
__device__ __nv_bfloat16 g_xhi[M_ * D_];
__device__ __nv_bfloat16 g_xlo[M_ * D_];
__device__ __nv_bfloat16 g_ahi[M_ * D_];
__device__ __nv_bfloat16 g_alo[M_ * D_];
__device__ __nv_bfloat16 g_wthi[4 * D_ * D_];   // W^T as [n][k], bf16 hi
__device__ __nv_bfloat16 g_wtlo[4 * D_ * D_];   // bf16 lo
__device__ __half g_qf[M_ * D_];                // Q/K/V single fp16, [B,H,S,HD]
__device__ __half g_kf[M_ * D_];
__device__ __half g_vf[M_ * D_];

// ---------------- helpers ---------------------------------------------------
__device__ __forceinline__ uint32_t smem_u32(const void* p) {
    uint32_t a;
    asm("{ .reg .u64 t; cvta.to.shared.u64 t, %1; cvt.u32.u64 %0, t; }"
        : "=r"(a) : "l"(p));
    return a;
}
__device__ __forceinline__ void cp16(uint32_t dst, const void* src) {
    asm volatile("cp.async.cg.shared.global [%0], [%1], 16;" :: "r"(dst), "l"(src));
}
__device__ __forceinline__ void cp_commit() {
    asm volatile("cp.async.commit_group;" ::: "memory");
}
__device__ __forceinline__ void cp_wait1() {
    asm volatile("cp.async.wait_group 1;" ::: "memory");
}
__device__ __forceinline__ void cp_wait0() {
    asm volatile("cp.async.wait_group 0;" ::: "memory");
}
__device__ __forceinline__ void ldsm4(uint32_t* r, uint32_t addr) {
    asm volatile("ldmatrix.sync.aligned.m8n8.x4.shared.b16 {%0,%1,%2,%3}, [%4];"
                 : "=r"(r[0]), "=r"(r[1]), "=r"(r[2]), "=r"(r[3]) : "r"(addr));
}
__device__ __forceinline__ void ldsm4t(uint32_t* r, uint32_t addr) {
    asm volatile("ldmatrix.sync.aligned.m8n8.x4.trans.shared.b16 {%0,%1,%2,%3}, [%4];"
                 : "=r"(r[0]), "=r"(r[1]), "=r"(r[2]), "=r"(r[3]) : "r"(addr));
}
__device__ __forceinline__ void mma16816(float* c, const uint32_t* a,
                                         uint32_t b0, uint32_t b1) {
    asm volatile(
        "mma.sync.aligned.m16n8k16.row.col.f32.bf16.bf16.f32 "
        "{%0,%1,%2,%3}, {%4,%5,%6,%7}, {%8,%9}, {%0,%1,%2,%3};"
        : "+f"(c[0]), "+f"(c[1]), "+f"(c[2]), "+f"(c[3])
        : "r"(a[0]), "r"(a[1]), "r"(a[2]), "r"(a[3]), "r"(b0), "r"(b1));
}
__device__ __forceinline__ void mma16816h(float* c, const uint32_t* a,
                                          uint32_t b0, uint32_t b1) {
    asm volatile(
        "mma.sync.aligned.m16n8k16.row.col.f32.f16.f16.f32 "
        "{%0,%1,%2,%3}, {%4,%5,%6,%7}, {%8,%9}, {%0,%1,%2,%3};"
        : "+f"(c[0]), "+f"(c[1]), "+f"(c[2]), "+f"(c[3])
        : "r"(a[0]), "r"(a[1]), "r"(a[2]), "r"(a[3]), "r"(b0), "r"(b1));
}
__device__ __forceinline__ float ex2f(float x) {
    float r;
    asm("ex2.approx.ftz.f32 %0, %1;" : "=f"(r) : "f"(x));
    return r;
}
// XOR swizzle for 128B rows (flash): 8 x 16B units
#define SWF(r, c) ((uint32_t)((r) * 128 + ((((c) ^ ((r) & 7))) << 4)))

__device__ __forceinline__ uint32_t pack_bf16_hi(float x, float y,
                                                 float& rx, float& ry) {
    __nv_bfloat16 hx = __float2bfloat16_rn(x);
    __nv_bfloat16 hy = __float2bfloat16_rn(y);
    rx = x - __bfloat162float(hx);
    ry = y - __bfloat162float(hy);
    __nv_bfloat162 p; p.x = hx; p.y = hy;
    return *(uint32_t*)&p;
}
__device__ __forceinline__ uint32_t pack_bf16(float x, float y) {
    __nv_bfloat162 p;
    p.x = __float2bfloat16_rn(x);
    p.y = __float2bfloat16_rn(y);
    return *(uint32_t*)&p;
}
__device__ __forceinline__ uint32_t pack_f16(float x, float y) {
    __half2 p = __floats2half2_rn(x, y);
    return *(uint32_t*)&p;
}

// ---------------------------------------------------------------------------
// Conversion kernels
// ---------------------------------------------------------------------------
__global__ void split_kernel(const float* __restrict__ src,
                             __nv_bfloat16* __restrict__ hi,
                             __nv_bfloat16* __restrict__ lo, int n)
{
    const int base = blockIdx.x * 4096 + threadIdx.x * 4;
#pragma unroll
    for (int p = 0; p < 4; p++) {
        const int i = base + p * 1024;
        if (i >= n) return;
        float4 v = *(const float4*)(src + i);
        float lx, ly, lz, lw;
        uint32_t h0 = pack_bf16_hi(v.x, v.y, lx, ly);
        uint32_t h1 = pack_bf16_hi(v.z, v.w, lz, lw);
        *(uint32_t*)(hi + i)     = h0;
        *(uint32_t*)(hi + i + 2) = h1;
        *(uint32_t*)(lo + i)     = pack_bf16(lx, ly);
        *(uint32_t*)(lo + i + 2) = pack_bf16(lz, lw);
    }
}

// W [k][n] fp32 -> W^T [n][k] bf16 hi/lo. Tile: 32 k x 64 n. 256 threads.
__global__ void transW_kernel(const float* __restrict__ W0, const float* __restrict__ W1,
                              const float* __restrict__ W2, const float* __restrict__ W3,
                              __nv_bfloat16* __restrict__ ohi, __nv_bfloat16* __restrict__ olo)
{
    __shared__ float t[32][65];
    const int z = blockIdx.z;
    const float* W = (z == 0) ? W0 : (z == 1) ? W1 : (z == 2) ? W2 : W3;
    const int n0 = blockIdx.x * 64, k0 = blockIdx.y * 32;
    const int tid = threadIdx.x;
#pragma unroll
    for (int p = 0; p < 8; p++) {
        const int lin = tid + p * 256;
        const int r = lin >> 6, c = lin & 63;
        t[r][c] = W[(size_t)(k0 + r) * D_ + n0 + c];
    }
    __syncthreads();
    __nv_bfloat16* Oh = ohi + (size_t)z * D_ * D_;
    __nv_bfloat16* Ol = olo + (size_t)z * D_ * D_;
    const int n = n0 + (tid >> 2);
    const int kb = (tid & 3) * 8;
    uint32_t hv[4], lv[4];
#pragma unroll
    for (int j = 0; j < 4; j++) {
        const float vx = t[kb + 2 * j][tid >> 2];
        const float vy = t[kb + 2 * j + 1][tid >> 2];
        float lx, ly;
        hv[j] = pack_bf16_hi(vx, vy, lx, ly);
        lv[j] = pack_bf16(lx, ly);
    }
    *(uint4*)&Oh[(size_t)n * D_ + k0 + kb] = *(uint4*)hv;
    *(uint4*)&Ol[(size_t)n * D_ + k0 + kb] = *(uint4*)lv;
}

// ---------------------------------------------------------------------------
// mma.sync bf16 GEMM (hi/lo split, 3 terms): C = A @ Wt^T + bias
// CTA 128x128, 256 threads (8 warps 4x2), BK=32.
// 64B smem rows, XOR swizzle, 3-stage distance-2 pipeline, one barrier/chunk.
// SCATTER=1: write single fp16 to [B,H,S,HD]; Q (z==0) pre-scaled.
// ---------------------------------------------------------------------------
#define GBUF (128 * 64)
#define GSTAGE (4 * GBUF)
#define GEMM_SMEM (3 * GSTAGE)
#define LOG2E 1.4426950408889634f

template <int SCATTER>
__global__ __launch_bounds__(256, 2) void gemm_mma_kernel(
    const __nv_bfloat16* __restrict__ Ah, const __nv_bfloat16* __restrict__ Al,
    const __nv_bfloat16* __restrict__ Wth, const __nv_bfloat16* __restrict__ Wtl,
    const float* __restrict__ b0p, const float* __restrict__ b1p,
    const float* __restrict__ b2p,
    float* __restrict__ fo,
    __half* __restrict__ of0, __half* __restrict__ of1, __half* __restrict__ of2)
{
    extern __shared__ __align__(16) char smem[];
    const uint32_t sbase = smem_u32(smem);
    const int tid  = threadIdx.x;
    const int wid  = tid >> 5;
    const int lane = tid & 31;
    const int wm   = wid & 3;
    const int wn   = wid >> 2;
    const int n0 = blockIdx.x * 128;
    const int m0 = blockIdx.y * 128;
    const int z  = blockIdx.z;

    const __nv_bfloat16* Bh = Wth + (size_t)z * D_ * D_;
    const __nv_bfloat16* Bl = Wtl + (size_t)z * D_ * D_;
    const float* bias = (z == 0) ? b0p : (z == 1) ? b1p : b2p;
    __half* Ofp = (z == 0) ? of0 : (z == 1) ? of1 : of2;
    const float scl = (SCATTER && z == 0) ? (0.125f * LOG2E) : 1.0f;

    float c[2][8][4];
#pragma unroll
    for (int i = 0; i < 2; i++)
#pragma unroll
        for (int j = 0; j < 8; j++)
#pragma unroll
            for (int q = 0; q < 4; q++) c[i][j][q] = 0.0f;

    const int u0 = tid * 2;
    auto load_chunk = [&](int stage, int kc) {
        const uint32_t sb = sbase + stage * GSTAGE;
#pragma unroll
        for (int u = 0; u < 2; u++) {
            const int idx = u0 + u;
            const int row = idx >> 2;
            const int c4  = idx & 3;
            const uint32_t off = (uint32_t)(row * 64 + ((c4 ^ ((row >> 1) & 3)) << 4));
            const size_t gA = (size_t)(m0 + row) * D_ + kc * 32 + c4 * 8;
            const size_t gB = (size_t)(n0 + row) * D_ + kc * 32 + c4 * 8;
            cp16(sb +            off, Ah + gA);
            cp16(sb + 1 * GBUF + off, Al + gA);
            cp16(sb + 2 * GBUF + off, Bh + gB);
            cp16(sb + 3 * GBUF + off, Bl + gB);
        }
        cp_commit();
    };

    const int a_rowb = wm * 32 + (lane & 15);
    const uint32_t a_mask = (uint32_t)(((lane & 15) >> 1) & 3);
    const uint32_t a_cu   = (uint32_t)(lane >> 4);
    const int b_rowb = wn * 64 + ((lane >> 4) & 1) * 8 + (lane & 7);
    const uint32_t b_mask = (uint32_t)(((lane & 7) >> 1) & 3);
    const uint32_t b_cu   = (uint32_t)((lane >> 3) & 1);

    const int NCHUNK = D_ / 32;   // 32
    load_chunk(0, 0);
    load_chunk(1, 1);

    for (int i = 0; i < NCHUNK; i++) {
        if (i + 1 < NCHUNK) cp_wait1(); else cp_wait0();
        __syncthreads();
        if (i + 2 < NCHUNK) load_chunk((i + 2) % 3, i + 2);

        const uint32_t stg = sbase + (i % 3) * GSTAGE;
        const uint32_t Abh = stg,             Abl = stg + 1u * GBUF;
        const uint32_t Bbh = stg + 2u * GBUF, Bbl = stg + 3u * GBUF;

#pragma unroll
        for (int kkb = 0; kkb < 2; kkb++) {
            const uint32_t acsw = (((uint32_t)(kkb * 2) + a_cu) ^ a_mask) << 4;
            const uint32_t bcsw = (((uint32_t)(kkb * 2) + b_cu) ^ b_mask) << 4;
            uint32_t ah[2][4], al[2][4];
            ldsm4(ah[0], Abh + (uint32_t)(a_rowb) * 64 + acsw);
            ldsm4(ah[1], Abh + (uint32_t)(a_rowb + 16) * 64 + acsw);
            ldsm4(al[0], Abl + (uint32_t)(a_rowb) * 64 + acsw);
            ldsm4(al[1], Abl + (uint32_t)(a_rowb + 16) * 64 + acsw);
#pragma unroll
            for (int half = 0; half < 2; half++) {
                uint32_t bh4[2][4], bl4[2][4];
#pragma unroll
                for (int p = 0; p < 2; p++) {
                    const int np = half * 2 + p;
                    ldsm4(bh4[p], Bbh + (uint32_t)(b_rowb + np * 16) * 64 + bcsw);
                    ldsm4(bl4[p], Bbl + (uint32_t)(b_rowb + np * 16) * 64 + bcsw);
                }
#pragma unroll
                for (int mt = 0; mt < 2; mt++)
#pragma unroll
                    for (int q = 0; q < 4; q++) {
                        const int nt = half * 4 + q;
                        const uint32_t b0h = bh4[q >> 1][(q & 1) * 2];
                        const uint32_t b1h = bh4[q >> 1][(q & 1) * 2 + 1];
                        const uint32_t b0l = bl4[q >> 1][(q & 1) * 2];
                        const uint32_t b1l = bl4[q >> 1][(q & 1) * 2 + 1];
                        float* cc = c[mt][nt];
                        mma16816(cc, ah[mt], b0h, b1h);
                        mma16816(cc, ah[mt], b0l, b1l);
                        mma16816(cc, al[mt], b0h, b1h);
                    }
            }
        }
    }

    const int nb = n0 + wn * 64;
#pragma unroll
    for (int mt = 0; mt < 2; mt++) {
        const int r0 = m0 + wm * 32 + mt * 16 + (lane >> 2);
#pragma unroll
        for (int nt = 0; nt < 8; nt++) {
            const int ng = nb + nt * 8 + (lane & 3) * 2;
            const float bx = bias[ng], by = bias[ng + 1];
            float v0x = (c[mt][nt][0] + bx) * scl, v0y = (c[mt][nt][1] + by) * scl;
            float v1x = (c[mt][nt][2] + bx) * scl, v1y = (c[mt][nt][3] + by) * scl;
            if (SCATTER) {
                const int h = ng >> 6;
                const int dd = ng & 63;
                const int bb0 = r0 >> 11, sI0 = r0 & (S_ - 1);
                const int r1 = r0 + 8;
                const int bb1 = r1 >> 11, sI1 = r1 & (S_ - 1);
                const size_t o0i = ((size_t)(bb0 * H_ + h) * S_ + sI0) * HD_ + dd;
                const size_t o1i = ((size_t)(bb1 * H_ + h) * S_ + sI1) * HD_ + dd;
                *(uint32_t*)&Ofp[o0i] = pack_f16(v0x, v0y);
                *(uint32_t*)&Ofp[o1i] = pack_f16(v1x, v1y);
            } else {
                *(float2*)&fo[(size_t)r0 * D_ + ng] = make_float2(v0x, v0y);
                *(float2*)&fo[(size_t)(r0 + 8) * D_ + ng] = make_float2(v1x, v1y);
            }
        }
    }
}

// ---------------------------------------------------------------------------
// Tensor-core flash attention, single fp16 Q/K/V (1-term QK^T, 1-term PV).
// CTA: 128 queries x one (b,h). 8 warps x 16 rows. Key blocks of 64,
// double-buffered. Log2-domain online softmax. Output att as bf16 hi/lo.
// ---------------------------------------------------------------------------
#define FL_QBUF 16384                  // 128 rows x 128B (fp16 HD=64)
#define FL_KVBUF 8192                  // 64 rows x 128B
#define FL_KVST (2 * FL_KVBUF)         // K,V = 16KB
#define FL_SMEM (FL_QBUF + 2 * FL_KVST)   // 48KB

__global__ __launch_bounds__(256) void flash_tc_kernel(
    const __half* __restrict__ Qf, const __half* __restrict__ Kf,
    const __half* __restrict__ Vf,
    __nv_bfloat16* __restrict__ Oh, __nv_bfloat16* __restrict__ Ol)
{
    extern __shared__ __align__(16) char smem[];
    const uint32_t base = smem_u32(smem);
    const int tid = threadIdx.x, wid = tid >> 5, lane = tid & 31;
    const int q0 = blockIdx.x * 128;
    const int bh = blockIdx.y;
    const size_t hb = (size_t)bh * S_ * HD_;

    // Q tile load (single fp16): 1024 x 16B
#pragma unroll
    for (int u = 0; u < 4; u++) {
        const int idx = tid + u * 256;
        const int r = idx >> 3;
        const int c = idx & 7;
        cp16(base + SWF(r, c), Qf + hb + (size_t)(q0 + r) * HD_ + c * 8);
    }
    cp_commit();

    auto loadkv = [&](int st, int kb) {
        const uint32_t sb = base + FL_QBUF + st * FL_KVST;
#pragma unroll
        for (int u = 0; u < 4; u++) {
            const int idx = tid + u * 256;   // 0..1023
            const int b2 = idx >> 9;         // 0=K, 1=V
            const int r = (idx >> 3) & 63;
            const int c = idx & 7;
            const __half* g = (b2 == 0) ? Kf : Vf;
            cp16(sb + b2 * FL_KVBUF + SWF(r, c),
                 g + hb + (size_t)(kb * 64 + r) * HD_ + c * 8);
        }
        cp_commit();
    };
    loadkv(0, 0);
    loadkv(1, 1);

    float o[8][4];
#pragma unroll
    for (int nt = 0; nt < 8; nt++)
#pragma unroll
        for (int q = 0; q < 4; q++) o[nt][q] = 0.0f;
    float m0r = -1e30f, m1r = -1e30f, l0 = 0.0f, l1 = 0.0f;

    const int a_row = wid * 16 + (lane & 7) + ((lane >> 3) & 1) * 8;
    const int a_c   = lane >> 4;
    const int k_row = ((lane >> 4) & 1) * 8 + (lane & 7);
    const int k_c   = (lane >> 3) & 1;
    const int v_row = ((lane >> 3) & 1) * 8 + (lane & 7);
    const int v_c   = lane >> 4;

    const int NB = S_ / 64;   // 32
    for (int kb = 0; kb < NB; kb++) {
        if (kb < NB - 1) cp_wait1(); else cp_wait0();
        __syncthreads();
        const uint32_t stg = base + FL_QBUF + (kb & 1) * FL_KVST;
        const uint32_t vbb = stg + FL_KVBUF;

        // ---- S = Q K^T (single fp16) ----
        float s[8][4];
#pragma unroll
        for (int nt = 0; nt < 8; nt++)
#pragma unroll
            for (int q = 0; q < 4; q++) s[nt][q] = 0.0f;

#pragma unroll
        for (int ks = 0; ks < 4; ks++) {
            uint32_t a4[4];
            ldsm4(a4, base + SWF(a_row, 2 * ks + a_c));
#pragma unroll
            for (int np = 0; np < 4; np++) {
                uint32_t b4[4];
                ldsm4(b4, stg + SWF(np * 16 + k_row, 2 * ks + k_c));
                mma16816h(s[2 * np],     a4, b4[0], b4[1]);
                mma16816h(s[2 * np + 1], a4, b4[2], b4[3]);
            }
        }

        // ---- online softmax (log2 domain) ----
        float mx0 = -1e30f, mx1 = -1e30f;
#pragma unroll
        for (int nt = 0; nt < 8; nt++) {
            mx0 = fmaxf(mx0, fmaxf(s[nt][0], s[nt][1]));
            mx1 = fmaxf(mx1, fmaxf(s[nt][2], s[nt][3]));
        }
        mx0 = fmaxf(mx0, __shfl_xor_sync(0xffffffffu, mx0, 1));
        mx0 = fmaxf(mx0, __shfl_xor_sync(0xffffffffu, mx0, 2));
        mx1 = fmaxf(mx1, __shfl_xor_sync(0xffffffffu, mx1, 1));
        mx1 = fmaxf(mx1, __shfl_xor_sync(0xffffffffu, mx1, 2));
        const float mn0 = fmaxf(m0r, mx0);
        const float mn1 = fmaxf(m1r, mx1);
        const float al0 = ex2f(m0r - mn0);
        const float al1 = ex2f(m1r - mn1);
        m0r = mn0; m1r = mn1;

        float sum0 = 0.0f, sum1 = 0.0f;
#pragma unroll
        for (int nt = 0; nt < 8; nt++) {
            s[nt][0] = ex2f(s[nt][0] - mn0);
            s[nt][1] = ex2f(s[nt][1] - mn0);
            s[nt][2] = ex2f(s[nt][2] - mn1);
            s[nt][3] = ex2f(s[nt][3] - mn1);
            sum0 += s[nt][0] + s[nt][1];
            sum1 += s[nt][2] + s[nt][3];
        }
        sum0 += __shfl_xor_sync(0xffffffffu, sum0, 1);
        sum0 += __shfl_xor_sync(0xffffffffu, sum0, 2);
        sum1 += __shfl_xor_sync(0xffffffffu, sum1, 1);
        sum1 += __shfl_xor_sync(0xffffffffu, sum1, 2);
        l0 = l0 * al0 + sum0;
        l1 = l1 * al1 + sum1;
#pragma unroll
        for (int nt = 0; nt < 8; nt++) {
            o[nt][0] *= al0; o[nt][1] *= al0;
            o[nt][2] *= al1; o[nt][3] *= al1;
        }

        // pack P as single fp16 fragments
        uint32_t ap[4][4];
#pragma unroll
        for (int kc = 0; kc < 4; kc++) {
            ap[kc][0] = pack_f16(s[2 * kc][0],     s[2 * kc][1]);
            ap[kc][1] = pack_f16(s[2 * kc][2],     s[2 * kc][3]);
            ap[kc][2] = pack_f16(s[2 * kc + 1][0], s[2 * kc + 1][1]);
            ap[kc][3] = pack_f16(s[2 * kc + 1][2], s[2 * kc + 1][3]);
        }

        // ---- O += P V (single fp16) ----
#pragma unroll
        for (int dp = 0; dp < 4; dp++) {
#pragma unroll
            for (int kc = 0; kc < 4; kc++) {
                uint32_t v4[4];
                ldsm4t(v4, vbb + SWF(kc * 16 + v_row, 2 * dp + v_c));
                mma16816h(o[2 * dp],     ap[kc], v4[0], v4[1]);
                mma16816h(o[2 * dp + 1], ap[kc], v4[2], v4[3]);
            }
        }
        __syncthreads();
        if (kb + 2 < NB) loadkv(kb & 1, kb + 2);
    }

    // ---- epilogue: /l, write bf16 hi/lo at [B,S,D] ----
    const float inv0 = 1.0f / l0, inv1 = 1.0f / l1;
    const int h = bh & (H_ - 1);
    const int bb = bh >> 4;
    const int r0 = q0 + wid * 16 + (lane >> 2);
    const int r1 = r0 + 8;
#pragma unroll
    for (int nt = 0; nt < 8; nt++) {
        const int gd = h * 64 + nt * 8 + (lane & 3) * 2;
        const size_t i0 = ((size_t)bb * S_ + r0) * D_ + gd;
        const size_t i1 = ((size_t)bb * S_ + r1) * D_ + gd;
        float lx, ly;
        *(uint32_t*)&Oh[i0] = pack_bf16_hi(o[nt][0] * inv0, o[nt][1] * inv0, lx, ly);
        *(uint32_t*)&Ol[i0] = pack_bf16(lx, ly);
        *(uint32_t*)&Oh[i1] = pack_bf16_hi(o[nt][2] * inv1, o[nt][3] * inv1, lx, ly);
        *(uint32_t*)&Ol[i1] = pack_bf16(lx, ly);
    }
}

// ---------------------------------------------------------------------------

extern "C" void kernel_launch(void* const* d_in, const int* in_sizes, int n_in,
                              void* d_out, int out_size)
{
    (void)in_sizes; (void)n_in; (void)out_size;
    const float* x  = (const float*)d_in[0];
    const float* Wq = (const float*)d_in[1];
    const float* bq = (const float*)d_in[2];
    const float* Wk = (const float*)d_in[3];
    const float* bk = (const float*)d_in[4];
    const float* Wv = (const float*)d_in[5];
    const float* bv = (const float*)d_in[6];
    const float* Wo = (const float*)d_in[7];
    const float* bo = (const float*)d_in[8];
    float* out = (float*)d_out;

    __nv_bfloat16 *xhi, *xlo, *ahi, *alo, *wthi, *wtlo;
    __half *qf, *kf, *vf;
    cudaGetSymbolAddress((void**)&xhi,  g_xhi);
    cudaGetSymbolAddress((void**)&xlo,  g_xlo);
    cudaGetSymbolAddress((void**)&ahi,  g_ahi);
    cudaGetSymbolAddress((void**)&alo,  g_alo);
    cudaGetSymbolAddress((void**)&wthi, g_wthi);
    cudaGetSymbolAddress((void**)&wtlo, g_wtlo);
    cudaGetSymbolAddress((void**)&qf,   g_qf);
    cudaGetSymbolAddress((void**)&kf,   g_kf);
    cudaGetSymbolAddress((void**)&vf,   g_vf);

    cudaFuncSetAttribute(gemm_mma_kernel<1>,
        cudaFuncAttributeMaxDynamicSharedMemorySize, GEMM_SMEM);
    cudaFuncSetAttribute(gemm_mma_kernel<0>,
        cudaFuncAttributeMaxDynamicSharedMemorySize, GEMM_SMEM);
    cudaFuncSetAttribute(flash_tc_kernel,
        cudaFuncAttributeMaxDynamicSharedMemorySize, FL_SMEM);

    const int NEL = M_ * D_;
    split_kernel<<<NEL / 4096, 256>>>(x, xhi, xlo, NEL);
    transW_kernel<<<dim3(16, 32, 4), 256>>>(Wq, Wk, Wv, Wo, wthi, wtlo);

    // Q,K,V projections -> single fp16, head-scattered, Q pre-scaled
    gemm_mma_kernel<1><<<dim3(8, 32, 3), 256, GEMM_SMEM>>>(
        xhi, xlo, wthi, wtlo, bq, bk, bv,
        nullptr, qf, kf, vf);

    flash_tc_kernel<<<dim3(S_ / 128, B_ * H_), 256, FL_SMEM>>>(
        qf, kf, vf, ahi, alo);

    gemm_mma_kernel<0><<<dim3(8, 32, 1), 256, GEMM_SMEM>>>(
        ahi, alo, wthi + (size_t)3 * D_ * D_, wtlo + (size_t)3 * D_ * D_,
        bo, bo, bo, out, nullptr, nullptr, nullptr);
}

// round 12
// speedup vs baseline: 1.4562x; 1.1407x over previous
#include <cuda_runtime.h>
#include <cuda_bf16.h>
#include <cuda_fp16.h>
#include <math.h>
#include <stdint.h>

#define B_ 2
#define S_ 2048
#define D_ 1024
#define H_ 16
#define HD_ 64
#define M_ 4096

// ---------------- scratch (__device__ globals; allocation-free rule) -------
__device__ __nv_bfloat16 g_xhi[M_ * D_];
__device__ __nv_bfloat16 g_xlo[M_ * D_];
__device__ __nv_bfloat16 g_wthi[3 * D_ * D_];   // Wq/Wk/Wv ^T [n][k], bf16 hi
__device__ __nv_bfloat16 g_wtlo[3 * D_ * D_];   // bf16 lo
__device__ __half g_wof[D_ * D_];               // Wo^T [n][k], fp16 single
__device__ __half g_qf[M_ * D_];                // Q/K/V single fp16, [B,H,S,HD]
__device__ __half g_kf[M_ * D_];
__device__ __half g_vf[M_ * D_];
__device__ __half g_af[M_ * D_];                // attended, fp16 [B,S,D]

// ---------------- helpers ---------------------------------------------------
__device__ __forceinline__ uint32_t smem_u32(const void* p) {
    uint32_t a;
    asm("{ .reg .u64 t; cvta.to.shared.u64 t, %1; cvt.u32.u64 %0, t; }"
        : "=r"(a) : "l"(p));
    return a;
}
__device__ __forceinline__ void cp16(uint32_t dst, const void* src) {
    asm volatile("cp.async.cg.shared.global [%0], [%1], 16;" :: "r"(dst), "l"(src));
}
__device__ __forceinline__ void cp_commit() {
    asm volatile("cp.async.commit_group;" ::: "memory");
}
__device__ __forceinline__ void cp_wait1() {
    asm volatile("cp.async.wait_group 1;" ::: "memory");
}
__device__ __forceinline__ void cp_wait0() {
    asm volatile("cp.async.wait_group 0;" ::: "memory");
}
__device__ __forceinline__ void ldsm4(uint32_t* r, uint32_t addr) {
    asm volatile("ldmatrix.sync.aligned.m8n8.x4.shared.b16 {%0,%1,%2,%3}, [%4];"
                 : "=r"(r[0]), "=r"(r[1]), "=r"(r[2]), "=r"(r[3]) : "r"(addr));
}
__device__ __forceinline__ void ldsm4t(uint32_t* r, uint32_t addr) {
    asm volatile("ldmatrix.sync.aligned.m8n8.x4.trans.shared.b16 {%0,%1,%2,%3}, [%4];"
                 : "=r"(r[0]), "=r"(r[1]), "=r"(r[2]), "=r"(r[3]) : "r"(addr));
}
__device__ __forceinline__ void mma16816(float* c, const uint32_t* a,
                                         uint32_t b0, uint32_t b1) {
    asm volatile(
        "mma.sync.aligned.m16n8k16.row.col.f32.bf16.bf16.f32 "
        "{%0,%1,%2,%3}, {%4,%5,%6,%7}, {%8,%9}, {%0,%1,%2,%3};"
        : "+f"(c[0]), "+f"(c[1]), "+f"(c[2]), "+f"(c[3])
        : "r"(a[0]), "r"(a[1]), "r"(a[2]), "r"(a[3]), "r"(b0), "r"(b1));
}
__device__ __forceinline__ void mma16816h(float* c, const uint32_t* a,
                                          uint32_t b0, uint32_t b1) {
    asm volatile(
        "mma.sync.aligned.m16n8k16.row.col.f32.f16.f16.f32 "
        "{%0,%1,%2,%3}, {%4,%5,%6,%7}, {%8,%9}, {%0,%1,%2,%3};"
        : "+f"(c[0]), "+f"(c[1]), "+f"(c[2]), "+f"(c[3])
        : "r"(a[0]), "r"(a[1]), "r"(a[2]), "r"(a[3]), "r"(b0), "r"(b1));
}
__device__ __forceinline__ float ex2f(float x) {
    float r;
    asm("ex2.approx.ftz.f32 %0, %1;" : "=f"(r) : "f"(x));
    return r;
}
// XOR swizzle for 128B rows (flash): 8 x 16B units
#define SWF(r, c) ((uint32_t)((r) * 128 + ((((c) ^ ((r) & 7))) << 4)))

__device__ __forceinline__ uint32_t pack_bf16_hi(float x, float y,
                                                 float& rx, float& ry) {
    __nv_bfloat16 hx = __float2bfloat16_rn(x);
    __nv_bfloat16 hy = __float2bfloat16_rn(y);
    rx = x - __bfloat162float(hx);
    ry = y - __bfloat162float(hy);
    __nv_bfloat162 p; p.x = hx; p.y = hy;
    return *(uint32_t*)&p;
}
__device__ __forceinline__ uint32_t pack_bf16(float x, float y) {
    __nv_bfloat162 p;
    p.x = __float2bfloat16_rn(x);
    p.y = __float2bfloat16_rn(y);
    return *(uint32_t*)&p;
}
__device__ __forceinline__ uint32_t pack_f16(float x, float y) {
    __half2 p = __floats2half2_rn(x, y);
    return *(uint32_t*)&p;
}

// ---------------------------------------------------------------------------
// Conversion kernels
// ---------------------------------------------------------------------------
__global__ void split_kernel(const float* __restrict__ src,
                             __nv_bfloat16* __restrict__ hi,
                             __nv_bfloat16* __restrict__ lo, int n)
{
    const int base = blockIdx.x * 4096 + threadIdx.x * 4;
#pragma unroll
    for (int p = 0; p < 4; p++) {
        const int i = base + p * 1024;
        if (i >= n) return;
        float4 v = *(const float4*)(src + i);
        float lx, ly, lz, lw;
        uint32_t h0 = pack_bf16_hi(v.x, v.y, lx, ly);
        uint32_t h1 = pack_bf16_hi(v.z, v.w, lz, lw);
        *(uint32_t*)(hi + i)     = h0;
        *(uint32_t*)(hi + i + 2) = h1;
        *(uint32_t*)(lo + i)     = pack_bf16(lx, ly);
        *(uint32_t*)(lo + i + 2) = pack_bf16(lz, lw);
    }
}

// W [k][n] fp32 -> W^T [n][k]. z<3: bf16 hi/lo; z==3 (Wo): fp16 single.
__global__ void transW_kernel(const float* __restrict__ W0, const float* __restrict__ W1,
                              const float* __restrict__ W2, const float* __restrict__ W3,
                              __nv_bfloat16* __restrict__ ohi, __nv_bfloat16* __restrict__ olo,
                              __half* __restrict__ wof)
{
    __shared__ float t[32][65];
    const int z = blockIdx.z;
    const float* W = (z == 0) ? W0 : (z == 1) ? W1 : (z == 2) ? W2 : W3;
    const int n0 = blockIdx.x * 64, k0 = blockIdx.y * 32;
    const int tid = threadIdx.x;
#pragma unroll
    for (int p = 0; p < 8; p++) {
        const int lin = tid + p * 256;
        const int r = lin >> 6, c = lin & 63;
        t[r][c] = W[(size_t)(k0 + r) * D_ + n0 + c];
    }
    __syncthreads();
    const int n = n0 + (tid >> 2);
    const int kb = (tid & 3) * 8;
    if (z == 3) {
        uint32_t fv[4];
#pragma unroll
        for (int j = 0; j < 4; j++)
            fv[j] = pack_f16(t[kb + 2 * j][tid >> 2], t[kb + 2 * j + 1][tid >> 2]);
        *(uint4*)&wof[(size_t)n * D_ + k0 + kb] = *(uint4*)fv;
    } else {
        __nv_bfloat16* Oh = ohi + (size_t)z * D_ * D_;
        __nv_bfloat16* Ol = olo + (size_t)z * D_ * D_;
        uint32_t hv[4], lv[4];
#pragma unroll
        for (int j = 0; j < 4; j++) {
            float lx, ly;
            hv[j] = pack_bf16_hi(t[kb + 2 * j][tid >> 2], t[kb + 2 * j + 1][tid >> 2], lx, ly);
            lv[j] = pack_bf16(lx, ly);
        }
        *(uint4*)&Oh[(size_t)n * D_ + k0 + kb] = *(uint4*)hv;
        *(uint4*)&Ol[(size_t)n * D_ + k0 + kb] = *(uint4*)lv;
    }
}

// ---------------------------------------------------------------------------
// QKV GEMM: mma.sync bf16 hi/lo 3-term, CTA 128x128, BK=32, 3-stage pipeline.
// Writes single fp16 to [B,H,S,HD]; Q (z==0) pre-scaled by 0.125*log2(e).
// ---------------------------------------------------------------------------
#define GBUF (128 * 64)
#define GSTAGE (4 * GBUF)
#define GEMM_SMEM (3 * GSTAGE)
#define LOG2E 1.4426950408889634f

__global__ __launch_bounds__(256, 2) void gemm_qkv_kernel(
    const __nv_bfloat16* __restrict__ Ah, const __nv_bfloat16* __restrict__ Al,
    const __nv_bfloat16* __restrict__ Wth, const __nv_bfloat16* __restrict__ Wtl,
    const float* __restrict__ b0p, const float* __restrict__ b1p,
    const float* __restrict__ b2p,
    __half* __restrict__ of0, __half* __restrict__ of1, __half* __restrict__ of2)
{
    extern __shared__ __align__(16) char smem[];
    const uint32_t sbase = smem_u32(smem);
    const int tid  = threadIdx.x;
    const int wid  = tid >> 5;
    const int lane = tid & 31;
    const int wm   = wid & 3;
    const int wn   = wid >> 2;
    const int n0 = blockIdx.x * 128;
    const int m0 = blockIdx.y * 128;
    const int z  = blockIdx.z;

    const __nv_bfloat16* Bh = Wth + (size_t)z * D_ * D_;
    const __nv_bfloat16* Bl = Wtl + (size_t)z * D_ * D_;
    const float* bias = (z == 0) ? b0p : (z == 1) ? b1p : b2p;
    __half* Ofp = (z == 0) ? of0 : (z == 1) ? of1 : of2;
    const float scl = (z == 0) ? (0.125f * LOG2E) : 1.0f;

    float c[2][8][4];
#pragma unroll
    for (int i = 0; i < 2; i++)
#pragma unroll
        for (int j = 0; j < 8; j++)
#pragma unroll
            for (int q = 0; q < 4; q++) c[i][j][q] = 0.0f;

    const int u0 = tid * 2;
    auto load_chunk = [&](int stage, int kc) {
        const uint32_t sb = sbase + stage * GSTAGE;
#pragma unroll
        for (int u = 0; u < 2; u++) {
            const int idx = u0 + u;
            const int row = idx >> 2;
            const int c4  = idx & 3;
            const uint32_t off = (uint32_t)(row * 64 + ((c4 ^ ((row >> 1) & 3)) << 4));
            const size_t gA = (size_t)(m0 + row) * D_ + kc * 32 + c4 * 8;
            const size_t gB = (size_t)(n0 + row) * D_ + kc * 32 + c4 * 8;
            cp16(sb +            off, Ah + gA);
            cp16(sb + 1 * GBUF + off, Al + gA);
            cp16(sb + 2 * GBUF + off, Bh + gB);
            cp16(sb + 3 * GBUF + off, Bl + gB);
        }
        cp_commit();
    };

    const int a_rowb = wm * 32 + (lane & 15);
    const uint32_t a_mask = (uint32_t)(((lane & 15) >> 1) & 3);
    const uint32_t a_cu   = (uint32_t)(lane >> 4);
    const int b_rowb = wn * 64 + ((lane >> 4) & 1) * 8 + (lane & 7);
    const uint32_t b_mask = (uint32_t)(((lane & 7) >> 1) & 3);
    const uint32_t b_cu   = (uint32_t)((lane >> 3) & 1);

    const int NCHUNK = D_ / 32;   // 32
    load_chunk(0, 0);
    load_chunk(1, 1);

    for (int i = 0; i < NCHUNK; i++) {
        if (i + 1 < NCHUNK) cp_wait1(); else cp_wait0();
        __syncthreads();
        if (i + 2 < NCHUNK) load_chunk((i + 2) % 3, i + 2);

        const uint32_t stg = sbase + (i % 3) * GSTAGE;
        const uint32_t Abh = stg,             Abl = stg + 1u * GBUF;
        const uint32_t Bbh = stg + 2u * GBUF, Bbl = stg + 3u * GBUF;

#pragma unroll
        for (int kkb = 0; kkb < 2; kkb++) {
            const uint32_t acsw = (((uint32_t)(kkb * 2) + a_cu) ^ a_mask) << 4;
            const uint32_t bcsw = (((uint32_t)(kkb * 2) + b_cu) ^ b_mask) << 4;
            uint32_t ah[2][4], al[2][4];
            ldsm4(ah[0], Abh + (uint32_t)(a_rowb) * 64 + acsw);
            ldsm4(ah[1], Abh + (uint32_t)(a_rowb + 16) * 64 + acsw);
            ldsm4(al[0], Abl + (uint32_t)(a_rowb) * 64 + acsw);
            ldsm4(al[1], Abl + (uint32_t)(a_rowb + 16) * 64 + acsw);
#pragma unroll
            for (int half = 0; half < 2; half++) {
                uint32_t bh4[2][4], bl4[2][4];
#pragma unroll
                for (int p = 0; p < 2; p++) {
                    const int np = half * 2 + p;
                    ldsm4(bh4[p], Bbh + (uint32_t)(b_rowb + np * 16) * 64 + bcsw);
                    ldsm4(bl4[p], Bbl + (uint32_t)(b_rowb + np * 16) * 64 + bcsw);
                }
#pragma unroll
                for (int mt = 0; mt < 2; mt++)
#pragma unroll
                    for (int q = 0; q < 4; q++) {
                        const int nt = half * 4 + q;
                        const uint32_t b0h = bh4[q >> 1][(q & 1) * 2];
                        const uint32_t b1h = bh4[q >> 1][(q & 1) * 2 + 1];
                        const uint32_t b0l = bl4[q >> 1][(q & 1) * 2];
                        const uint32_t b1l = bl4[q >> 1][(q & 1) * 2 + 1];
                        float* cc = c[mt][nt];
                        mma16816(cc, ah[mt], b0h, b1h);
                        mma16816(cc, ah[mt], b0l, b1l);
                        mma16816(cc, al[mt], b0h, b1h);
                    }
            }
        }
    }

    const int nb = n0 + wn * 64;
#pragma unroll
    for (int mt = 0; mt < 2; mt++) {
        const int r0 = m0 + wm * 32 + mt * 16 + (lane >> 2);
#pragma unroll
        for (int nt = 0; nt < 8; nt++) {
            const int ng = nb + nt * 8 + (lane & 3) * 2;
            const float bx = bias[ng], by = bias[ng + 1];
            const int h = ng >> 6;
            const int dd = ng & 63;
            const int bb0 = r0 >> 11, sI0 = r0 & (S_ - 1);
            const int r1 = r0 + 8;
            const int bb1 = r1 >> 11, sI1 = r1 & (S_ - 1);
            const size_t o0i = ((size_t)(bb0 * H_ + h) * S_ + sI0) * HD_ + dd;
            const size_t o1i = ((size_t)(bb1 * H_ + h) * S_ + sI1) * HD_ + dd;
            *(uint32_t*)&Ofp[o0i] =
                pack_f16((c[mt][nt][0] + bx) * scl, (c[mt][nt][1] + by) * scl);
            *(uint32_t*)&Ofp[o1i] =
                pack_f16((c[mt][nt][2] + bx) * scl, (c[mt][nt][3] + by) * scl);
        }
    }
}

// ---------------------------------------------------------------------------
// Output GEMM: single fp16 1-term. out[M,D] = att @ Wo^T + bo (fp32 out).
// CTA 128x128, BK=32, 3-stage pipeline (2 buffers/stage).
// ---------------------------------------------------------------------------
#define OBUF (128 * 64)
#define OSTAGE (2 * OBUF)
#define OGEMM_SMEM (3 * OSTAGE)   // 49152

__global__ __launch_bounds__(256, 2) void gemm_out_kernel(
    const __half* __restrict__ Af, const __half* __restrict__ Wof,
    const float* __restrict__ bias, float* __restrict__ out)
{
    extern __shared__ __align__(16) char smem[];
    const uint32_t sbase = smem_u32(smem);
    const int tid  = threadIdx.x;
    const int wid  = tid >> 5;
    const int lane = tid & 31;
    const int wm   = wid & 3;
    const int wn   = wid >> 2;
    const int n0 = blockIdx.x * 128;
    const int m0 = blockIdx.y * 128;

    float c[2][8][4];
#pragma unroll
    for (int i = 0; i < 2; i++)
#pragma unroll
        for (int j = 0; j < 8; j++)
#pragma unroll
            for (int q = 0; q < 4; q++) c[i][j][q] = 0.0f;

    const int u0 = tid;   // 256 threads x 1 16B unit per buffer
    auto load_chunk = [&](int stage, int kc) {
        const uint32_t sb = sbase + stage * OSTAGE;
        const int row = u0 >> 2;        // wait: 256 threads cover 1024 units? No.
        (void)row;
#pragma unroll
        for (int u = 0; u < 2; u++) {
            const int idx = tid * 2 + u;      // 0..511
            const int r = idx >> 2;
            const int c4 = idx & 3;
            const uint32_t off = (uint32_t)(r * 64 + ((c4 ^ ((r >> 1) & 3)) << 4));
            cp16(sb +        off, Af  + (size_t)(m0 + r) * D_ + kc * 32 + c4 * 8);
            cp16(sb + OBUF + off, Wof + (size_t)(n0 + r) * D_ + kc * 32 + c4 * 8);
        }
        cp_commit();
    };

    const int a_rowb = wm * 32 + (lane & 15);
    const uint32_t a_mask = (uint32_t)(((lane & 15) >> 1) & 3);
    const uint32_t a_cu   = (uint32_t)(lane >> 4);
    const int b_rowb = wn * 64 + ((lane >> 4) & 1) * 8 + (lane & 7);
    const uint32_t b_mask = (uint32_t)(((lane & 7) >> 1) & 3);
    const uint32_t b_cu   = (uint32_t)((lane >> 3) & 1);

    const int NCHUNK = D_ / 32;
    load_chunk(0, 0);
    load_chunk(1, 1);

    for (int i = 0; i < NCHUNK; i++) {
        if (i + 1 < NCHUNK) cp_wait1(); else cp_wait0();
        __syncthreads();
        if (i + 2 < NCHUNK) load_chunk((i + 2) % 3, i + 2);

        const uint32_t stg = sbase + (i % 3) * OSTAGE;
        const uint32_t Ab = stg, Bb = stg + OBUF;

#pragma unroll
        for (int kkb = 0; kkb < 2; kkb++) {
            const uint32_t acsw = (((uint32_t)(kkb * 2) + a_cu) ^ a_mask) << 4;
            const uint32_t bcsw = (((uint32_t)(kkb * 2) + b_cu) ^ b_mask) << 4;
            uint32_t a4[2][4];
            ldsm4(a4[0], Ab + (uint32_t)(a_rowb) * 64 + acsw);
            ldsm4(a4[1], Ab + (uint32_t)(a_rowb + 16) * 64 + acsw);
#pragma unroll
            for (int half = 0; half < 2; half++) {
                uint32_t b4[2][4];
#pragma unroll
                for (int p = 0; p < 2; p++) {
                    const int np = half * 2 + p;
                    ldsm4(b4[p], Bb + (uint32_t)(b_rowb + np * 16) * 64 + bcsw);
                }
#pragma unroll
                for (int mt = 0; mt < 2; mt++)
#pragma unroll
                    for (int q = 0; q < 4; q++) {
                        const int nt = half * 4 + q;
                        mma16816h(c[mt][nt], a4[mt],
                                  b4[q >> 1][(q & 1) * 2], b4[q >> 1][(q & 1) * 2 + 1]);
                    }
            }
        }
    }

    const int nb = n0 + wn * 64;
#pragma unroll
    for (int mt = 0; mt < 2; mt++) {
        const int r0 = m0 + wm * 32 + mt * 16 + (lane >> 2);
#pragma unroll
        for (int nt = 0; nt < 8; nt++) {
            const int ng = nb + nt * 8 + (lane & 3) * 2;
            const float bx = bias[ng], by = bias[ng + 1];
            *(float2*)&out[(size_t)r0 * D_ + ng] =
                make_float2(c[mt][nt][0] + bx, c[mt][nt][1] + by);
            *(float2*)&out[(size_t)(r0 + 8) * D_ + ng] =
                make_float2(c[mt][nt][2] + bx, c[mt][nt][3] + by);
        }
    }
}

// ---------------------------------------------------------------------------
// Tensor-core flash attention, single fp16, 3-stage KV ring (one barrier/iter).
// CTA: 128 queries x one (b,h). 8 warps x 16 rows. Key blocks of 64.
// Output att as single fp16 at [B,S,D].
// ---------------------------------------------------------------------------
#define FL_QBUF 16384                  // 128 rows x 128B
#define FL_KVBUF 8192                  // 64 rows x 128B
#define FL_KVST (2 * FL_KVBUF)         // K,V = 16KB
#define FL_SMEM (FL_QBUF + 3 * FL_KVST)   // 64KB

__global__ __launch_bounds__(256) void flash_tc_kernel(
    const __half* __restrict__ Qf, const __half* __restrict__ Kf,
    const __half* __restrict__ Vf, __half* __restrict__ Af)
{
    extern __shared__ __align__(16) char smem[];
    const uint32_t base = smem_u32(smem);
    const int tid = threadIdx.x, wid = tid >> 5, lane = tid & 31;
    const int q0 = blockIdx.x * 128;
    const int bh = blockIdx.y;
    const size_t hb = (size_t)bh * S_ * HD_;

#pragma unroll
    for (int u = 0; u < 4; u++) {
        const int idx = tid + u * 256;
        const int r = idx >> 3;
        const int c = idx & 7;
        cp16(base + SWF(r, c), Qf + hb + (size_t)(q0 + r) * HD_ + c * 8);
    }
    cp_commit();

    auto loadkv = [&](int st, int kb) {
        const uint32_t sb = base + FL_QBUF + st * FL_KVST;
#pragma unroll
        for (int u = 0; u < 4; u++) {
            const int idx = tid + u * 256;
            const int b2 = idx >> 9;
            const int r = (idx >> 3) & 63;
            const int c = idx & 7;
            const __half* g = (b2 == 0) ? Kf : Vf;
            cp16(sb + b2 * FL_KVBUF + SWF(r, c),
                 g + hb + (size_t)(kb * 64 + r) * HD_ + c * 8);
        }
        cp_commit();
    };
    loadkv(0, 0);
    loadkv(1, 1);

    float o[8][4];
#pragma unroll
    for (int nt = 0; nt < 8; nt++)
#pragma unroll
        for (int q = 0; q < 4; q++) o[nt][q] = 0.0f;
    float m0r = -1e30f, m1r = -1e30f, l0 = 0.0f, l1 = 0.0f;

    const int a_row = wid * 16 + (lane & 7) + ((lane >> 3) & 1) * 8;
    const int a_c   = lane >> 4;
    const int k_row = ((lane >> 4) & 1) * 8 + (lane & 7);
    const int k_c   = (lane >> 3) & 1;
    const int v_row = ((lane >> 3) & 1) * 8 + (lane & 7);
    const int v_c   = lane >> 4;

    const int NB = S_ / 64;   // 32
    for (int kb = 0; kb < NB; kb++) {
        if (kb < NB - 1) cp_wait1(); else cp_wait0();
        __syncthreads();
        if (kb + 2 < NB) loadkv((kb + 2) % 3, kb + 2);

        const uint32_t stg = base + FL_QBUF + (kb % 3) * FL_KVST;
        const uint32_t vbb = stg + FL_KVBUF;

        float s[8][4];
#pragma unroll
        for (int nt = 0; nt < 8; nt++)
#pragma unroll
            for (int q = 0; q < 4; q++) s[nt][q] = 0.0f;

#pragma unroll
        for (int ks = 0; ks < 4; ks++) {
            uint32_t a4[4];
            ldsm4(a4, base + SWF(a_row, 2 * ks + a_c));
#pragma unroll
            for (int np = 0; np < 4; np++) {
                uint32_t b4[4];
                ldsm4(b4, stg + SWF(np * 16 + k_row, 2 * ks + k_c));
                mma16816h(s[2 * np],     a4, b4[0], b4[1]);
                mma16816h(s[2 * np + 1], a4, b4[2], b4[3]);
            }
        }

        float mx0 = -1e30f, mx1 = -1e30f;
#pragma unroll
        for (int nt = 0; nt < 8; nt++) {
            mx0 = fmaxf(mx0, fmaxf(s[nt][0], s[nt][1]));
            mx1 = fmaxf(mx1, fmaxf(s[nt][2], s[nt][3]));
        }
        mx0 = fmaxf(mx0, __shfl_xor_sync(0xffffffffu, mx0, 1));
        mx0 = fmaxf(mx0, __shfl_xor_sync(0xffffffffu, mx0, 2));
        mx1 = fmaxf(mx1, __shfl_xor_sync(0xffffffffu, mx1, 1));
        mx1 = fmaxf(mx1, __shfl_xor_sync(0xffffffffu, mx1, 2));
        const float mn0 = fmaxf(m0r, mx0);
        const float mn1 = fmaxf(m1r, mx1);
        const float al0 = ex2f(m0r - mn0);
        const float al1 = ex2f(m1r - mn1);
        m0r = mn0; m1r = mn1;

        float sum0 = 0.0f, sum1 = 0.0f;
#pragma unroll
        for (int nt = 0; nt < 8; nt++) {
            s[nt][0] = ex2f(s[nt][0] - mn0);
            s[nt][1] = ex2f(s[nt][1] - mn0);
            s[nt][2] = ex2f(s[nt][2] - mn1);
            s[nt][3] = ex2f(s[nt][3] - mn1);
            sum0 += s[nt][0] + s[nt][1];
            sum1 += s[nt][2] + s[nt][3];
        }
        sum0 += __shfl_xor_sync(0xffffffffu, sum0, 1);
        sum0 += __shfl_xor_sync(0xffffffffu, sum0, 2);
        sum1 += __shfl_xor_sync(0xffffffffu, sum1, 1);
        sum1 += __shfl_xor_sync(0xffffffffu, sum1, 2);
        l0 = l0 * al0 + sum0;
        l1 = l1 * al1 + sum1;
#pragma unroll
        for (int nt = 0; nt < 8; nt++) {
            o[nt][0] *= al0; o[nt][1] *= al0;
            o[nt][2] *= al1; o[nt][3] *= al1;
        }

        uint32_t ap[4][4];
#pragma unroll
        for (int kc = 0; kc < 4; kc++) {
            ap[kc][0] = pack_f16(s[2 * kc][0],     s[2 * kc][1]);
            ap[kc][1] = pack_f16(s[2 * kc][2],     s[2 * kc][3]);
            ap[kc][2] = pack_f16(s[2 * kc + 1][0], s[2 * kc + 1][1]);
            ap[kc][3] = pack_f16(s[2 * kc + 1][2], s[2 * kc + 1][3]);
        }

#pragma unroll
        for (int dp = 0; dp < 4; dp++) {
#pragma unroll
            for (int kc = 0; kc < 4; kc++) {
                uint32_t v4[4];
                ldsm4t(v4, vbb + SWF(kc * 16 + v_row, 2 * dp + v_c));
                mma16816h(o[2 * dp],     ap[kc], v4[0], v4[1]);
                mma16816h(o[2 * dp + 1], ap[kc], v4[2], v4[3]);
            }
        }
        // no trailing sync: next load targets stage (kb+2)%3, untouched by readers
    }

    const float inv0 = 1.0f / l0, inv1 = 1.0f / l1;
    const int h = bh & (H_ - 1);
    const int bb = bh >> 4;
    const int r0 = q0 + wid * 16 + (lane >> 2);
    const int r1 = r0 + 8;
#pragma unroll
    for (int nt = 0; nt < 8; nt++) {
        const int gd = h * 64 + nt * 8 + (lane & 3) * 2;
        const size_t i0 = ((size_t)bb * S_ + r0) * D_ + gd;
        const size_t i1 = ((size_t)bb * S_ + r1) * D_ + gd;
        *(uint32_t*)&Af[i0] = pack_f16(o[nt][0] * inv0, o[nt][1] * inv0);
        *(uint32_t*)&Af[i1] = pack_f16(o[nt][2] * inv1, o[nt][3] * inv1);
    }
}

// ---------------------------------------------------------------------------

extern "C" void kernel_launch(void* const* d_in, const int* in_sizes, int n_in,
                              void* d_out, int out_size)
{
    (void)in_sizes; (void)n_in; (void)out_size;
    const float* x  = (const float*)d_in[0];
    const float* Wq = (const float*)d_in[1];
    const float* bq = (const float*)d_in[2];
    const float* Wk = (const float*)d_in[3];
    const float* bk = (const float*)d_in[4];
    const float* Wv = (const float*)d_in[5];
    const float* bv = (const float*)d_in[6];
    const float* Wo = (const float*)d_in[7];
    const float* bo = (const float*)d_in[8];
    float* out = (float*)d_out;

    __nv_bfloat16 *xhi, *xlo, *wthi, *wtlo;
    __half *wof, *qf, *kf, *vf, *af;
    cudaGetSymbolAddress((void**)&xhi,  g_xhi);
    cudaGetSymbolAddress((void**)&xlo,  g_xlo);
    cudaGetSymbolAddress((void**)&wthi, g_wthi);
    cudaGetSymbolAddress((void**)&wtlo, g_wtlo);
    cudaGetSymbolAddress((void**)&wof,  g_wof);
    cudaGetSymbolAddress((void**)&qf,   g_qf);
    cudaGetSymbolAddress((void**)&kf,   g_kf);
    cudaGetSymbolAddress((void**)&vf,   g_vf);
    cudaGetSymbolAddress((void**)&af,   g_af);

    cudaFuncSetAttribute(gemm_qkv_kernel,
        cudaFuncAttributeMaxDynamicSharedMemorySize, GEMM_SMEM);
    cudaFuncSetAttribute(gemm_out_kernel,
        cudaFuncAttributeMaxDynamicSharedMemorySize, OGEMM_SMEM);
    cudaFuncSetAttribute(flash_tc_kernel,
        cudaFuncAttributeMaxDynamicSharedMemorySize, FL_SMEM);

    const int NEL = M_ * D_;
    split_kernel<<<NEL / 4096, 256>>>(x, xhi, xlo, NEL);
    transW_kernel<<<dim3(16, 32, 4), 256>>>(Wq, Wk, Wv, Wo, wthi, wtlo, wof);

    gemm_qkv_kernel<<<dim3(8, 32, 3), 256, GEMM_SMEM>>>(
        xhi, xlo, wthi, wtlo, bq, bk, bv, qf, kf, vf);

    flash_tc_kernel<<<dim3(S_ / 128, B_ * H_), 256, FL_SMEM>>>(qf, kf, vf, af);

    gemm_out_kernel<<<dim3(8, 32), 256, OGEMM_SMEM>>>(af, wof, bo, out);
}

// round 13
// speedup vs baseline: 1.4670x; 1.0074x over previous
#include <cuda_runtime.h>
#include <cuda_bf16.h>
#include <cuda_fp16.h>
#include <math.h>
#include <stdint.h>

#define B_ 2
#define S_ 2048
#define D_ 1024
#define H_ 16
#define HD_ 64
#define M_ 4096

// ---------------- scratch (__device__ globals; allocation-free rule) -------
__device__ __nv_bfloat16 g_xhi[M_ * D_];
__device__ __nv_bfloat16 g_xlo[M_ * D_];
__device__ __nv_bfloat16 g_wthi[3 * D_ * D_];   // Wq/Wk/Wv ^T [n][k], bf16 hi
__device__ __nv_bfloat16 g_wtlo[3 * D_ * D_];   // bf16 lo
__device__ __half g_wof[D_ * D_];               // Wo^T [n][k], fp16 single
__device__ __half g_qf[M_ * D_];                // Q/K/V single fp16, [B,H,S,HD]
__device__ __half g_kf[M_ * D_];
__device__ __half g_vf[M_ * D_];
__device__ __half g_af[M_ * D_];                // attended, fp16 [B,S,D]

// ---------------- helpers ---------------------------------------------------
__device__ __forceinline__ uint32_t smem_u32(const void* p) {
    uint32_t a;
    asm("{ .reg .u64 t; cvta.to.shared.u64 t, %1; cvt.u32.u64 %0, t; }"
        : "=r"(a) : "l"(p));
    return a;
}
__device__ __forceinline__ void cp16(uint32_t dst, const void* src) {
    asm volatile("cp.async.cg.shared.global [%0], [%1], 16;" :: "r"(dst), "l"(src));
}
__device__ __forceinline__ void cp_commit() {
    asm volatile("cp.async.commit_group;" ::: "memory");
}
__device__ __forceinline__ void cp_wait1() {
    asm volatile("cp.async.wait_group 1;" ::: "memory");
}
__device__ __forceinline__ void cp_wait0() {
    asm volatile("cp.async.wait_group 0;" ::: "memory");
}
__device__ __forceinline__ void ldsm4(uint32_t* r, uint32_t addr) {
    asm volatile("ldmatrix.sync.aligned.m8n8.x4.shared.b16 {%0,%1,%2,%3}, [%4];"
                 : "=r"(r[0]), "=r"(r[1]), "=r"(r[2]), "=r"(r[3]) : "r"(addr));
}
__device__ __forceinline__ void ldsm4t(uint32_t* r, uint32_t addr) {
    asm volatile("ldmatrix.sync.aligned.m8n8.x4.trans.shared.b16 {%0,%1,%2,%3}, [%4];"
                 : "=r"(r[0]), "=r"(r[1]), "=r"(r[2]), "=r"(r[3]) : "r"(addr));
}
__device__ __forceinline__ void mma16816(float* c, const uint32_t* a,
                                         uint32_t b0, uint32_t b1) {
    asm volatile(
        "mma.sync.aligned.m16n8k16.row.col.f32.bf16.bf16.f32 "
        "{%0,%1,%2,%3}, {%4,%5,%6,%7}, {%8,%9}, {%0,%1,%2,%3};"
        : "+f"(c[0]), "+f"(c[1]), "+f"(c[2]), "+f"(c[3])
        : "r"(a[0]), "r"(a[1]), "r"(a[2]), "r"(a[3]), "r"(b0), "r"(b1));
}
__device__ __forceinline__ void mma16816h(float* c, const uint32_t* a,
                                          uint32_t b0, uint32_t b1) {
    asm volatile(
        "mma.sync.aligned.m16n8k16.row.col.f32.f16.f16.f32 "
        "{%0,%1,%2,%3}, {%4,%5,%6,%7}, {%8,%9}, {%0,%1,%2,%3};"
        : "+f"(c[0]), "+f"(c[1]), "+f"(c[2]), "+f"(c[3])
        : "r"(a[0]), "r"(a[1]), "r"(a[2]), "r"(a[3]), "r"(b0), "r"(b1));
}
__device__ __forceinline__ float ex2f(float x) {
    float r;
    asm("ex2.approx.ftz.f32 %0, %1;" : "=f"(r) : "f"(x));
    return r;
}
// Pack two fp32 exponent args to fp16x2 and exponentiate: returns {2^lo, 2^hi} fp16x2
__device__ __forceinline__ uint32_t ex2_pack(float a_lo, float a_hi) {
    uint32_t h;
    asm("{ .reg .b32 t;\n\t"
        "cvt.rn.f16x2.f32 t, %2, %1;\n\t"
        "ex2.approx.f16x2 t, t;\n\t"
        "mov.b32 %0, t; }"
        : "=r"(h) : "f"(a_lo), "f"(a_hi));
    return h;
}
// XOR swizzle for 128B rows (flash): 8 x 16B units
#define SWF(r, c) ((uint32_t)((r) * 128 + ((((c) ^ ((r) & 7))) << 4)))

__device__ __forceinline__ uint32_t pack_bf16_hi(float x, float y,
                                                 float& rx, float& ry) {
    __nv_bfloat16 hx = __float2bfloat16_rn(x);
    __nv_bfloat16 hy = __float2bfloat16_rn(y);
    rx = x - __bfloat162float(hx);
    ry = y - __bfloat162float(hy);
    __nv_bfloat162 p; p.x = hx; p.y = hy;
    return *(uint32_t*)&p;
}
__device__ __forceinline__ uint32_t pack_bf16(float x, float y) {
    __nv_bfloat162 p;
    p.x = __float2bfloat16_rn(x);
    p.y = __float2bfloat16_rn(y);
    return *(uint32_t*)&p;
}
__device__ __forceinline__ uint32_t pack_f16(float x, float y) {
    __half2 p = __floats2half2_rn(x, y);
    return *(uint32_t*)&p;
}

// ---------------------------------------------------------------------------
// Conversion kernels
// ---------------------------------------------------------------------------
__global__ void split_kernel(const float* __restrict__ src,
                             __nv_bfloat16* __restrict__ hi,
                             __nv_bfloat16* __restrict__ lo, int n)
{
    const int base = blockIdx.x * 4096 + threadIdx.x * 4;
#pragma unroll
    for (int p = 0; p < 4; p++) {
        const int i = base + p * 1024;
        if (i >= n) return;
        float4 v = *(const float4*)(src + i);
        float lx, ly, lz, lw;
        uint32_t h0 = pack_bf16_hi(v.x, v.y, lx, ly);
        uint32_t h1 = pack_bf16_hi(v.z, v.w, lz, lw);
        *(uint32_t*)(hi + i)     = h0;
        *(uint32_t*)(hi + i + 2) = h1;
        *(uint32_t*)(lo + i)     = pack_bf16(lx, ly);
        *(uint32_t*)(lo + i + 2) = pack_bf16(lz, lw);
    }
}

// W [k][n] fp32 -> W^T [n][k]. z<3: bf16 hi/lo; z==3 (Wo): fp16 single.
__global__ void transW_kernel(const float* __restrict__ W0, const float* __restrict__ W1,
                              const float* __restrict__ W2, const float* __restrict__ W3,
                              __nv_bfloat16* __restrict__ ohi, __nv_bfloat16* __restrict__ olo,
                              __half* __restrict__ wof)
{
    __shared__ float t[32][65];
    const int z = blockIdx.z;
    const float* W = (z == 0) ? W0 : (z == 1) ? W1 : (z == 2) ? W2 : W3;
    const int n0 = blockIdx.x * 64, k0 = blockIdx.y * 32;
    const int tid = threadIdx.x;
#pragma unroll
    for (int p = 0; p < 8; p++) {
        const int lin = tid + p * 256;
        const int r = lin >> 6, c = lin & 63;
        t[r][c] = W[(size_t)(k0 + r) * D_ + n0 + c];
    }
    __syncthreads();
    const int n = n0 + (tid >> 2);
    const int kb = (tid & 3) * 8;
    if (z == 3) {
        uint32_t fv[4];
#pragma unroll
        for (int j = 0; j < 4; j++)
            fv[j] = pack_f16(t[kb + 2 * j][tid >> 2], t[kb + 2 * j + 1][tid >> 2]);
        *(uint4*)&wof[(size_t)n * D_ + k0 + kb] = *(uint4*)fv;
    } else {
        __nv_bfloat16* Oh = ohi + (size_t)z * D_ * D_;
        __nv_bfloat16* Ol = olo + (size_t)z * D_ * D_;
        uint32_t hv[4], lv[4];
#pragma unroll
        for (int j = 0; j < 4; j++) {
            float lx, ly;
            hv[j] = pack_bf16_hi(t[kb + 2 * j][tid >> 2], t[kb + 2 * j + 1][tid >> 2], lx, ly);
            lv[j] = pack_bf16(lx, ly);
        }
        *(uint4*)&Oh[(size_t)n * D_ + k0 + kb] = *(uint4*)hv;
        *(uint4*)&Ol[(size_t)n * D_ + k0 + kb] = *(uint4*)lv;
    }
}

// ---------------------------------------------------------------------------
// QKV GEMM: mma.sync bf16 hi/lo 3-term, CTA 128x128, BK=32, 3-stage pipeline.
// Writes single fp16 to [B,H,S,HD]; Q (z==0) pre-scaled by 0.125*log2(e).
// ---------------------------------------------------------------------------
#define GBUF (128 * 64)
#define GSTAGE (4 * GBUF)
#define GEMM_SMEM (3 * GSTAGE)
#define LOG2E 1.4426950408889634f

__global__ __launch_bounds__(256, 2) void gemm_qkv_kernel(
    const __nv_bfloat16* __restrict__ Ah, const __nv_bfloat16* __restrict__ Al,
    const __nv_bfloat16* __restrict__ Wth, const __nv_bfloat16* __restrict__ Wtl,
    const float* __restrict__ b0p, const float* __restrict__ b1p,
    const float* __restrict__ b2p,
    __half* __restrict__ of0, __half* __restrict__ of1, __half* __restrict__ of2)
{
    extern __shared__ __align__(16) char smem[];
    const uint32_t sbase = smem_u32(smem);
    const int tid  = threadIdx.x;
    const int wid  = tid >> 5;
    const int lane = tid & 31;
    const int wm   = wid & 3;
    const int wn   = wid >> 2;
    const int n0 = blockIdx.x * 128;
    const int m0 = blockIdx.y * 128;
    const int z  = blockIdx.z;

    const __nv_bfloat16* Bh = Wth + (size_t)z * D_ * D_;
    const __nv_bfloat16* Bl = Wtl + (size_t)z * D_ * D_;
    const float* bias = (z == 0) ? b0p : (z == 1) ? b1p : b2p;
    __half* Ofp = (z == 0) ? of0 : (z == 1) ? of1 : of2;
    const float scl = (z == 0) ? (0.125f * LOG2E) : 1.0f;

    float c[2][8][4];
#pragma unroll
    for (int i = 0; i < 2; i++)
#pragma unroll
        for (int j = 0; j < 8; j++)
#pragma unroll
            for (int q = 0; q < 4; q++) c[i][j][q] = 0.0f;

    const int u0 = tid * 2;
    auto load_chunk = [&](int stage, int kc) {
        const uint32_t sb = sbase + stage * GSTAGE;
#pragma unroll
        for (int u = 0; u < 2; u++) {
            const int idx = u0 + u;
            const int row = idx >> 2;
            const int c4  = idx & 3;
            const uint32_t off = (uint32_t)(row * 64 + ((c4 ^ ((row >> 1) & 3)) << 4));
            const size_t gA = (size_t)(m0 + row) * D_ + kc * 32 + c4 * 8;
            const size_t gB = (size_t)(n0 + row) * D_ + kc * 32 + c4 * 8;
            cp16(sb +            off, Ah + gA);
            cp16(sb + 1 * GBUF + off, Al + gA);
            cp16(sb + 2 * GBUF + off, Bh + gB);
            cp16(sb + 3 * GBUF + off, Bl + gB);
        }
        cp_commit();
    };

    const int a_rowb = wm * 32 + (lane & 15);
    const uint32_t a_mask = (uint32_t)(((lane & 15) >> 1) & 3);
    const uint32_t a_cu   = (uint32_t)(lane >> 4);
    const int b_rowb = wn * 64 + ((lane >> 4) & 1) * 8 + (lane & 7);
    const uint32_t b_mask = (uint32_t)(((lane & 7) >> 1) & 3);
    const uint32_t b_cu   = (uint32_t)((lane >> 3) & 1);

    const int NCHUNK = D_ / 32;   // 32
    load_chunk(0, 0);
    load_chunk(1, 1);

    for (int i = 0; i < NCHUNK; i++) {
        if (i + 1 < NCHUNK) cp_wait1(); else cp_wait0();
        __syncthreads();
        if (i + 2 < NCHUNK) load_chunk((i + 2) % 3, i + 2);

        const uint32_t stg = sbase + (i % 3) * GSTAGE;
        const uint32_t Abh = stg,             Abl = stg + 1u * GBUF;
        const uint32_t Bbh = stg + 2u * GBUF, Bbl = stg + 3u * GBUF;

#pragma unroll
        for (int kkb = 0; kkb < 2; kkb++) {
            const uint32_t acsw = (((uint32_t)(kkb * 2) + a_cu) ^ a_mask) << 4;
            const uint32_t bcsw = (((uint32_t)(kkb * 2) + b_cu) ^ b_mask) << 4;
            uint32_t ah[2][4], al[2][4];
            ldsm4(ah[0], Abh + (uint32_t)(a_rowb) * 64 + acsw);
            ldsm4(ah[1], Abh + (uint32_t)(a_rowb + 16) * 64 + acsw);
            ldsm4(al[0], Abl + (uint32_t)(a_rowb) * 64 + acsw);
            ldsm4(al[1], Abl + (uint32_t)(a_rowb + 16) * 64 + acsw);
#pragma unroll
            for (int half = 0; half < 2; half++) {
                uint32_t bh4[2][4], bl4[2][4];
#pragma unroll
                for (int p = 0; p < 2; p++) {
                    const int np = half * 2 + p;
                    ldsm4(bh4[p], Bbh + (uint32_t)(b_rowb + np * 16) * 64 + bcsw);
                    ldsm4(bl4[p], Bbl + (uint32_t)(b_rowb + np * 16) * 64 + bcsw);
                }
#pragma unroll
                for (int mt = 0; mt < 2; mt++)
#pragma unroll
                    for (int q = 0; q < 4; q++) {
                        const int nt = half * 4 + q;
                        const uint32_t b0h = bh4[q >> 1][(q & 1) * 2];
                        const uint32_t b1h = bh4[q >> 1][(q & 1) * 2 + 1];
                        const uint32_t b0l = bl4[q >> 1][(q & 1) * 2];
                        const uint32_t b1l = bl4[q >> 1][(q & 1) * 2 + 1];
                        float* cc = c[mt][nt];
                        mma16816(cc, ah[mt], b0h, b1h);
                        mma16816(cc, ah[mt], b0l, b1l);
                        mma16816(cc, al[mt], b0h, b1h);
                    }
            }
        }
    }

    const int nb = n0 + wn * 64;
#pragma unroll
    for (int mt = 0; mt < 2; mt++) {
        const int r0 = m0 + wm * 32 + mt * 16 + (lane >> 2);
#pragma unroll
        for (int nt = 0; nt < 8; nt++) {
            const int ng = nb + nt * 8 + (lane & 3) * 2;
            const float bx = bias[ng], by = bias[ng + 1];
            const int h = ng >> 6;
            const int dd = ng & 63;
            const int bb0 = r0 >> 11, sI0 = r0 & (S_ - 1);
            const int r1 = r0 + 8;
            const int bb1 = r1 >> 11, sI1 = r1 & (S_ - 1);
            const size_t o0i = ((size_t)(bb0 * H_ + h) * S_ + sI0) * HD_ + dd;
            const size_t o1i = ((size_t)(bb1 * H_ + h) * S_ + sI1) * HD_ + dd;
            *(uint32_t*)&Ofp[o0i] =
                pack_f16((c[mt][nt][0] + bx) * scl, (c[mt][nt][1] + by) * scl);
            *(uint32_t*)&Ofp[o1i] =
                pack_f16((c[mt][nt][2] + bx) * scl, (c[mt][nt][3] + by) * scl);
        }
    }
}

// ---------------------------------------------------------------------------
// Output GEMM: single fp16 1-term. out[M,D] = att @ Wo^T + bo (fp32 out).
// ---------------------------------------------------------------------------
#define OBUF (128 * 64)
#define OSTAGE (2 * OBUF)
#define OGEMM_SMEM (3 * OSTAGE)   // 49152

__global__ __launch_bounds__(256, 2) void gemm_out_kernel(
    const __half* __restrict__ Af, const __half* __restrict__ Wof,
    const float* __restrict__ bias, float* __restrict__ out)
{
    extern __shared__ __align__(16) char smem[];
    const uint32_t sbase = smem_u32(smem);
    const int tid  = threadIdx.x;
    const int wid  = tid >> 5;
    const int lane = tid & 31;
    const int wm   = wid & 3;
    const int wn   = wid >> 2;
    const int n0 = blockIdx.x * 128;
    const int m0 = blockIdx.y * 128;

    float c[2][8][4];
#pragma unroll
    for (int i = 0; i < 2; i++)
#pragma unroll
        for (int j = 0; j < 8; j++)
#pragma unroll
            for (int q = 0; q < 4; q++) c[i][j][q] = 0.0f;

    auto load_chunk = [&](int stage, int kc) {
        const uint32_t sb = sbase + stage * OSTAGE;
#pragma unroll
        for (int u = 0; u < 2; u++) {
            const int idx = tid * 2 + u;      // 0..511
            const int r = idx >> 2;
            const int c4 = idx & 3;
            const uint32_t off = (uint32_t)(r * 64 + ((c4 ^ ((r >> 1) & 3)) << 4));
            cp16(sb +        off, Af  + (size_t)(m0 + r) * D_ + kc * 32 + c4 * 8);
            cp16(sb + OBUF + off, Wof + (size_t)(n0 + r) * D_ + kc * 32 + c4 * 8);
        }
        cp_commit();
    };

    const int a_rowb = wm * 32 + (lane & 15);
    const uint32_t a_mask = (uint32_t)(((lane & 15) >> 1) & 3);
    const uint32_t a_cu   = (uint32_t)(lane >> 4);
    const int b_rowb = wn * 64 + ((lane >> 4) & 1) * 8 + (lane & 7);
    const uint32_t b_mask = (uint32_t)(((lane & 7) >> 1) & 3);
    const uint32_t b_cu   = (uint32_t)((lane >> 3) & 1);

    const int NCHUNK = D_ / 32;
    load_chunk(0, 0);
    load_chunk(1, 1);

    for (int i = 0; i < NCHUNK; i++) {
        if (i + 1 < NCHUNK) cp_wait1(); else cp_wait0();
        __syncthreads();
        if (i + 2 < NCHUNK) load_chunk((i + 2) % 3, i + 2);

        const uint32_t stg = sbase + (i % 3) * OSTAGE;
        const uint32_t Ab = stg, Bb = stg + OBUF;

#pragma unroll
        for (int kkb = 0; kkb < 2; kkb++) {
            const uint32_t acsw = (((uint32_t)(kkb * 2) + a_cu) ^ a_mask) << 4;
            const uint32_t bcsw = (((uint32_t)(kkb * 2) + b_cu) ^ b_mask) << 4;
            uint32_t a4[2][4];
            ldsm4(a4[0], Ab + (uint32_t)(a_rowb) * 64 + acsw);
            ldsm4(a4[1], Ab + (uint32_t)(a_rowb + 16) * 64 + acsw);
#pragma unroll
            for (int half = 0; half < 2; half++) {
                uint32_t b4[2][4];
#pragma unroll
                for (int p = 0; p < 2; p++) {
                    const int np = half * 2 + p;
                    ldsm4(b4[p], Bb + (uint32_t)(b_rowb + np * 16) * 64 + bcsw);
                }
#pragma unroll
                for (int mt = 0; mt < 2; mt++)
#pragma unroll
                    for (int q = 0; q < 4; q++) {
                        const int nt = half * 4 + q;
                        mma16816h(c[mt][nt], a4[mt],
                                  b4[q >> 1][(q & 1) * 2], b4[q >> 1][(q & 1) * 2 + 1]);
                    }
            }
        }
    }

    const int nb = n0 + wn * 64;
#pragma unroll
    for (int mt = 0; mt < 2; mt++) {
        const int r0 = m0 + wm * 32 + mt * 16 + (lane >> 2);
#pragma unroll
        for (int nt = 0; nt < 8; nt++) {
            const int ng = nb + nt * 8 + (lane & 3) * 2;
            const float bx = bias[ng], by = bias[ng + 1];
            *(float2*)&out[(size_t)r0 * D_ + ng] =
                make_float2(c[mt][nt][0] + bx, c[mt][nt][1] + by);
            *(float2*)&out[(size_t)(r0 + 8) * D_ + ng] =
                make_float2(c[mt][nt][2] + bx, c[mt][nt][3] + by);
        }
    }
}

// ---------------------------------------------------------------------------
// Tensor-core flash attention, single fp16, 3-stage KV ring.
// Softmax: f16x2 ex2 (P fragments produced directly), l accumulated via an
// extra ones-column mma (no sum shuffles).
// ---------------------------------------------------------------------------
#define FL_QBUF 16384
#define FL_KVBUF 8192
#define FL_KVST (2 * FL_KVBUF)
#define FL_SMEM (FL_QBUF + 3 * FL_KVST)   // 64KB
#define ONES_F16X2 0x3C003C00u

__global__ __launch_bounds__(256) void flash_tc_kernel(
    const __half* __restrict__ Qf, const __half* __restrict__ Kf,
    const __half* __restrict__ Vf, __half* __restrict__ Af)
{
    extern __shared__ __align__(16) char smem[];
    const uint32_t base = smem_u32(smem);
    const int tid = threadIdx.x, wid = tid >> 5, lane = tid & 31;
    const int q0 = blockIdx.x * 128;
    const int bh = blockIdx.y;
    const size_t hb = (size_t)bh * S_ * HD_;

#pragma unroll
    for (int u = 0; u < 4; u++) {
        const int idx = tid + u * 256;
        const int r = idx >> 3;
        const int c = idx & 7;
        cp16(base + SWF(r, c), Qf + hb + (size_t)(q0 + r) * HD_ + c * 8);
    }
    cp_commit();

    auto loadkv = [&](int st, int kb) {
        const uint32_t sb = base + FL_QBUF + st * FL_KVST;
#pragma unroll
        for (int u = 0; u < 4; u++) {
            const int idx = tid + u * 256;
            const int b2 = idx >> 9;
            const int r = (idx >> 3) & 63;
            const int c = idx & 7;
            const __half* g = (b2 == 0) ? Kf : Vf;
            cp16(sb + b2 * FL_KVBUF + SWF(r, c),
                 g + hb + (size_t)(kb * 64 + r) * HD_ + c * 8);
        }
        cp_commit();
    };
    loadkv(0, 0);
    loadkv(1, 1);

    float o[8][4];
#pragma unroll
    for (int nt = 0; nt < 8; nt++)
#pragma unroll
        for (int q = 0; q < 4; q++) o[nt][q] = 0.0f;
    float ol[4] = {0.0f, 0.0f, 0.0f, 0.0f};   // l accumulator via ones-mma
    float m0r = -1e30f, m1r = -1e30f;

    const int a_row = wid * 16 + (lane & 7) + ((lane >> 3) & 1) * 8;
    const int a_c   = lane >> 4;
    const int k_row = ((lane >> 4) & 1) * 8 + (lane & 7);
    const int k_c   = (lane >> 3) & 1;
    const int v_row = ((lane >> 3) & 1) * 8 + (lane & 7);
    const int v_c   = lane >> 4;

    const int NB = S_ / 64;   // 32
    for (int kb = 0; kb < NB; kb++) {
        if (kb < NB - 1) cp_wait1(); else cp_wait0();
        __syncthreads();
        if (kb + 2 < NB) loadkv((kb + 2) % 3, kb + 2);

        const uint32_t stg = base + FL_QBUF + (kb % 3) * FL_KVST;
        const uint32_t vbb = stg + FL_KVBUF;

        float s[8][4];
#pragma unroll
        for (int nt = 0; nt < 8; nt++)
#pragma unroll
            for (int q = 0; q < 4; q++) s[nt][q] = 0.0f;

#pragma unroll
        for (int ks = 0; ks < 4; ks++) {
            uint32_t a4[4];
            ldsm4(a4, base + SWF(a_row, 2 * ks + a_c));
#pragma unroll
            for (int np = 0; np < 4; np++) {
                uint32_t b4[4];
                ldsm4(b4, stg + SWF(np * 16 + k_row, 2 * ks + k_c));
                mma16816h(s[2 * np],     a4, b4[0], b4[1]);
                mma16816h(s[2 * np + 1], a4, b4[2], b4[3]);
            }
        }

        // ---- max update (log2 domain) ----
        float mx0 = -1e30f, mx1 = -1e30f;
#pragma unroll
        for (int nt = 0; nt < 8; nt++) {
            mx0 = fmaxf(mx0, fmaxf(s[nt][0], s[nt][1]));
            mx1 = fmaxf(mx1, fmaxf(s[nt][2], s[nt][3]));
        }
        mx0 = fmaxf(mx0, __shfl_xor_sync(0xffffffffu, mx0, 1));
        mx0 = fmaxf(mx0, __shfl_xor_sync(0xffffffffu, mx0, 2));
        mx1 = fmaxf(mx1, __shfl_xor_sync(0xffffffffu, mx1, 1));
        mx1 = fmaxf(mx1, __shfl_xor_sync(0xffffffffu, mx1, 2));
        const float mn0 = fmaxf(m0r, mx0);
        const float mn1 = fmaxf(m1r, mx1);
        const float al0 = ex2f(m0r - mn0);
        const float al1 = ex2f(m1r - mn1);
        m0r = mn0; m1r = mn1;

        // rescale O and l accumulators
#pragma unroll
        for (int nt = 0; nt < 8; nt++) {
            o[nt][0] *= al0; o[nt][1] *= al0;
            o[nt][2] *= al1; o[nt][3] *= al1;
        }
        ol[0] *= al0; ol[1] *= al0;
        ol[2] *= al1; ol[3] *= al1;

        // ---- P fragments via f16x2 ex2 (direct fragment production) ----
        uint32_t ap[4][4];
#pragma unroll
        for (int kc = 0; kc < 4; kc++) {
            ap[kc][0] = ex2_pack(s[2 * kc][0] - mn0,     s[2 * kc][1] - mn0);
            ap[kc][1] = ex2_pack(s[2 * kc][2] - mn1,     s[2 * kc][3] - mn1);
            ap[kc][2] = ex2_pack(s[2 * kc + 1][0] - mn0, s[2 * kc + 1][1] - mn0);
            ap[kc][3] = ex2_pack(s[2 * kc + 1][2] - mn1, s[2 * kc + 1][3] - mn1);
        }

        // ---- l += P @ ones (tensor-core row sum; no shuffles) ----
#pragma unroll
        for (int kc = 0; kc < 4; kc++)
            mma16816h(ol, ap[kc], ONES_F16X2, ONES_F16X2);

        // ---- O += P V ----
#pragma unroll
        for (int dp = 0; dp < 4; dp++) {
#pragma unroll
            for (int kc = 0; kc < 4; kc++) {
                uint32_t v4[4];
                ldsm4t(v4, vbb + SWF(kc * 16 + v_row, 2 * dp + v_c));
                mma16816h(o[2 * dp],     ap[kc], v4[0], v4[1]);
                mma16816h(o[2 * dp + 1], ap[kc], v4[2], v4[3]);
            }
        }
        // no trailing sync: next load targets stage (kb+2)%3, untouched by readers
    }

    const float inv0 = 1.0f / ol[0];   // all cols of ones-mma equal the row sum
    const float inv1 = 1.0f / ol[2];
    const int h = bh & (H_ - 1);
    const int bb = bh >> 4;
    const int r0 = q0 + wid * 16 + (lane >> 2);
    const int r1 = r0 + 8;
#pragma unroll
    for (int nt = 0; nt < 8; nt++) {
        const int gd = h * 64 + nt * 8 + (lane & 3) * 2;
        const size_t i0 = ((size_t)bb * S_ + r0) * D_ + gd;
        const size_t i1 = ((size_t)bb * S_ + r1) * D_ + gd;
        *(uint32_t*)&Af[i0] = pack_f16(o[nt][0] * inv0, o[nt][1] * inv0);
        *(uint32_t*)&Af[i1] = pack_f16(o[nt][2] * inv1, o[nt][3] * inv1);
    }
}

// ---------------------------------------------------------------------------

extern "C" void kernel_launch(void* const* d_in, const int* in_sizes, int n_in,
                              void* d_out, int out_size)
{
    (void)in_sizes; (void)n_in; (void)out_size;
    const float* x  = (const float*)d_in[0];
    const float* Wq = (const float*)d_in[1];
    const float* bq = (const float*)d_in[2];
    const float* Wk = (const float*)d_in[3];
    const float* bk = (const float*)d_in[4];
    const float* Wv = (const float*)d_in[5];
    const float* bv = (const float*)d_in[6];
    const float* Wo = (const float*)d_in[7];
    const float* bo = (const float*)d_in[8];
    float* out = (float*)d_out;

    __nv_bfloat16 *xhi, *xlo, *wthi, *wtlo;
    __half *wof, *qf, *kf, *vf, *af;
    cudaGetSymbolAddress((void**)&xhi,  g_xhi);
    cudaGetSymbolAddress((void**)&xlo,  g_xlo);
    cudaGetSymbolAddress((void**)&wthi, g_wthi);
    cudaGetSymbolAddress((void**)&wtlo, g_wtlo);
    cudaGetSymbolAddress((void**)&wof,  g_wof);
    cudaGetSymbolAddress((void**)&qf,   g_qf);
    cudaGetSymbolAddress((void**)&kf,   g_kf);
    cudaGetSymbolAddress((void**)&vf,   g_vf);
    cudaGetSymbolAddress((void**)&af,   g_af);

    cudaFuncSetAttribute(gemm_qkv_kernel,
        cudaFuncAttributeMaxDynamicSharedMemorySize, GEMM_SMEM);
    cudaFuncSetAttribute(gemm_out_kernel,
        cudaFuncAttributeMaxDynamicSharedMemorySize, OGEMM_SMEM);
    cudaFuncSetAttribute(flash_tc_kernel,
        cudaFuncAttributeMaxDynamicSharedMemorySize, FL_SMEM);

    const int NEL = M_ * D_;
    split_kernel<<<NEL / 4096, 256>>>(x, xhi, xlo, NEL);
    transW_kernel<<<dim3(16, 32, 4), 256>>>(Wq, Wk, Wv, Wo, wthi, wtlo, wof);

    gemm_qkv_kernel<<<dim3(8, 32, 3), 256, GEMM_SMEM>>>(
        xhi, xlo, wthi, wtlo, bq, bk, bv, qf, kf, vf);

    flash_tc_kernel<<<dim3(S_ / 128, B_ * H_), 256, FL_SMEM>>>(qf, kf, vf, af);

    gemm_out_kernel<<<dim3(8, 32), 256, OGEMM_SMEM>>>(af, wof, bo, out);
}

// round 15
// speedup vs baseline: 1.7977x; 1.2255x over previous
#include <cuda_runtime.h>
#include <cuda_bf16.h>
#include <cuda_fp16.h>
#include <math.h>
#include <stdint.h>

#define B_ 2
#define S_ 2048
#define D_ 1024
#define H_ 16
#define HD_ 64
#define M_ 4096

// ---------------- scratch (__device__ globals; allocation-free rule) -------
__device__ __half g_xf[M_ * D_];                // x as single fp16
__device__ __half g_wqh[3 * D_ * D_];           // Wq/Wk/Wv ^T [n][k], fp16 hi
__device__ __half g_wql[3 * D_ * D_];           // fp16 lo (residual)
__device__ __half g_wof[D_ * D_];               // Wo^T [n][k], fp16 single
__device__ __half g_qf[M_ * D_];                // Q/K/V single fp16, [B,H,S,HD]
__device__ __half g_kf[M_ * D_];
__device__ __half g_vf[M_ * D_];
__device__ __half g_af[M_ * D_];                // attended, fp16 [B,S,D]

// ---------------- helpers ---------------------------------------------------
__device__ __forceinline__ uint32_t smem_u32(const void* p) {
    uint32_t a;
    asm("{ .reg .u64 t; cvta.to.shared.u64 t, %1; cvt.u32.u64 %0, t; }"
        : "=r"(a) : "l"(p));
    return a;
}
__device__ __forceinline__ void cp16(uint32_t dst, const void* src) {
    asm volatile("cp.async.cg.shared.global [%0], [%1], 16;" :: "r"(dst), "l"(src));
}
__device__ __forceinline__ void cp_commit() {
    asm volatile("cp.async.commit_group;" ::: "memory");
}
__device__ __forceinline__ void cp_wait1() {
    asm volatile("cp.async.wait_group 1;" ::: "memory");
}
__device__ __forceinline__ void cp_wait0() {
    asm volatile("cp.async.wait_group 0;" ::: "memory");
}
__device__ __forceinline__ void ldsm4(uint32_t* r, uint32_t addr) {
    asm volatile("ldmatrix.sync.aligned.m8n8.x4.shared.b16 {%0,%1,%2,%3}, [%4];"
                 : "=r"(r[0]), "=r"(r[1]), "=r"(r[2]), "=r"(r[3]) : "r"(addr));
}
__device__ __forceinline__ void ldsm4t(uint32_t* r, uint32_t addr) {
    asm volatile("ldmatrix.sync.aligned.m8n8.x4.trans.shared.b16 {%0,%1,%2,%3}, [%4];"
                 : "=r"(r[0]), "=r"(r[1]), "=r"(r[2]), "=r"(r[3]) : "r"(addr));
}
__device__ __forceinline__ void mma16816h(float* c, const uint32_t* a,
                                          uint32_t b0, uint32_t b1) {
    asm volatile(
        "mma.sync.aligned.m16n8k16.row.col.f32.f16.f16.f32 "
        "{%0,%1,%2,%3}, {%4,%5,%6,%7}, {%8,%9}, {%0,%1,%2,%3};"
        : "+f"(c[0]), "+f"(c[1]), "+f"(c[2]), "+f"(c[3])
        : "r"(a[0]), "r"(a[1]), "r"(a[2]), "r"(a[3]), "r"(b0), "r"(b1));
}
__device__ __forceinline__ float ex2f(float x) {
    float r;
    asm("ex2.approx.ftz.f32 %0, %1;" : "=f"(r) : "f"(x));
    return r;
}
// Pack two fp32 exponent args to fp16x2 and exponentiate
__device__ __forceinline__ uint32_t ex2_pack(float a_lo, float a_hi) {
    uint32_t h;
    asm("{ .reg .b32 t;\n\t"
        "cvt.rn.f16x2.f32 t, %2, %1;\n\t"
        "ex2.approx.f16x2 t, t;\n\t"
        "mov.b32 %0, t; }"
        : "=r"(h) : "f"(a_lo), "f"(a_hi));
    return h;
}
// XOR swizzle for 128B rows (flash): 8 x 16B units
#define SWF(r, c) ((uint32_t)((r) * 128 + ((((c) ^ ((r) & 7))) << 4)))

__device__ __forceinline__ uint32_t pack_f16(float x, float y) {
    __half2 p = __floats2half2_rn(x, y);
    return *(uint32_t*)&p;
}
__device__ __forceinline__ uint32_t pack_f16_hi(float x, float y,
                                                float& rx, float& ry) {
    __half hx = __float2half_rn(x);
    __half hy = __float2half_rn(y);
    rx = x - __half2float(hx);
    ry = y - __half2float(hy);
    __half2 p; p.x = hx; p.y = hy;
    return *(uint32_t*)&p;
}

// ---------------------------------------------------------------------------
// Conversion kernels
// ---------------------------------------------------------------------------
__global__ void cvt_kernel(const float* __restrict__ src,
                           __half* __restrict__ dst, int n)
{
    const int base = blockIdx.x * 4096 + threadIdx.x * 4;
#pragma unroll
    for (int p = 0; p < 4; p++) {
        const int i = base + p * 1024;
        if (i >= n) return;
        float4 v = *(const float4*)(src + i);
        *(uint32_t*)(dst + i)     = pack_f16(v.x, v.y);
        *(uint32_t*)(dst + i + 2) = pack_f16(v.z, v.w);
    }
}

// W [k][n] fp32 -> W^T [n][k]. z<3: fp16 hi/lo; z==3 (Wo): fp16 single.
__global__ void transW_kernel(const float* __restrict__ W0, const float* __restrict__ W1,
                              const float* __restrict__ W2, const float* __restrict__ W3,
                              __half* __restrict__ owh, __half* __restrict__ owl,
                              __half* __restrict__ wof)
{
    __shared__ float t[32][65];
    const int z = blockIdx.z;
    const float* W = (z == 0) ? W0 : (z == 1) ? W1 : (z == 2) ? W2 : W3;
    const int n0 = blockIdx.x * 64, k0 = blockIdx.y * 32;
    const int tid = threadIdx.x;
#pragma unroll
    for (int p = 0; p < 8; p++) {
        const int lin = tid + p * 256;
        const int r = lin >> 6, c = lin & 63;
        t[r][c] = W[(size_t)(k0 + r) * D_ + n0 + c];
    }
    __syncthreads();
    const int n = n0 + (tid >> 2);
    const int kb = (tid & 3) * 8;
    if (z == 3) {
        uint32_t fv[4];
#pragma unroll
        for (int j = 0; j < 4; j++)
            fv[j] = pack_f16(t[kb + 2 * j][tid >> 2], t[kb + 2 * j + 1][tid >> 2]);
        *(uint4*)&wof[(size_t)n * D_ + k0 + kb] = *(uint4*)fv;
    } else {
        __half* Oh = owh + (size_t)z * D_ * D_;
        __half* Ol = owl + (size_t)z * D_ * D_;
        uint32_t hv[4], lv[4];
#pragma unroll
        for (int j = 0; j < 4; j++) {
            float lx, ly;
            hv[j] = pack_f16_hi(t[kb + 2 * j][tid >> 2], t[kb + 2 * j + 1][tid >> 2], lx, ly);
            lv[j] = pack_f16(lx, ly);
        }
        *(uint4*)&Oh[(size_t)n * D_ + k0 + kb] = *(uint4*)hv;
        *(uint4*)&Ol[(size_t)n * D_ + k0 + kb] = *(uint4*)lv;
    }
}

// ---------------------------------------------------------------------------
// QKV GEMM: fp16 2-term (A single fp16, W fp16 hi/lo).
// CTA 128x128, BK=32, 3-stage pipeline (3 buffers/stage: A, Wh, Wl).
// Writes single fp16 to [B,H,S,HD]; Q (z==0) pre-scaled by 0.125*log2(e).
// ---------------------------------------------------------------------------
#define QBUF (128 * 64)
#define QSTAGE (3 * QBUF)          // 24576
#define QGEMM_SMEM (3 * QSTAGE)    // 73728
#define LOG2E 1.4426950408889634f

__global__ __launch_bounds__(256, 2) void gemm_qkv_kernel(
    const __half* __restrict__ Af, const __half* __restrict__ Wh,
    const __half* __restrict__ Wl,
    const float* __restrict__ b0p, const float* __restrict__ b1p,
    const float* __restrict__ b2p,
    __half* __restrict__ of0, __half* __restrict__ of1, __half* __restrict__ of2)
{
    extern __shared__ __align__(16) char smem[];
    const uint32_t sbase = smem_u32(smem);
    const int tid  = threadIdx.x;
    const int wid  = tid >> 5;
    const int lane = tid & 31;
    const int wm   = wid & 3;
    const int wn   = wid >> 2;
    const int n0 = blockIdx.x * 128;
    const int m0 = blockIdx.y * 128;
    const int z  = blockIdx.z;

    const __half* Bh = Wh + (size_t)z * D_ * D_;
    const __half* Bl = Wl + (size_t)z * D_ * D_;
    const float* bias = (z == 0) ? b0p : (z == 1) ? b1p : b2p;
    __half* Ofp = (z == 0) ? of0 : (z == 1) ? of1 : of2;
    const float scl = (z == 0) ? (0.125f * LOG2E) : 1.0f;

    float c[2][8][4];
#pragma unroll
    for (int i = 0; i < 2; i++)
#pragma unroll
        for (int j = 0; j < 8; j++)
#pragma unroll
            for (int q = 0; q < 4; q++) c[i][j][q] = 0.0f;

    const int u0 = tid * 2;
    auto load_chunk = [&](int stage, int kc) {
        const uint32_t sb = sbase + stage * QSTAGE;
#pragma unroll
        for (int u = 0; u < 2; u++) {
            const int idx = u0 + u;
            const int row = idx >> 2;
            const int c4  = idx & 3;
            const uint32_t off = (uint32_t)(row * 64 + ((c4 ^ ((row >> 1) & 3)) << 4));
            const size_t gA = (size_t)(m0 + row) * D_ + kc * 32 + c4 * 8;
            const size_t gB = (size_t)(n0 + row) * D_ + kc * 32 + c4 * 8;
            cp16(sb +            off, Af + gA);
            cp16(sb + 1 * QBUF + off, Bh + gB);
            cp16(sb + 2 * QBUF + off, Bl + gB);
        }
        cp_commit();
    };

    const int a_rowb = wm * 32 + (lane & 15);
    const uint32_t a_mask = (uint32_t)(((lane & 15) >> 1) & 3);
    const uint32_t a_cu   = (uint32_t)(lane >> 4);
    const int b_rowb = wn * 64 + ((lane >> 4) & 1) * 8 + (lane & 7);
    const uint32_t b_mask = (uint32_t)(((lane & 7) >> 1) & 3);
    const uint32_t b_cu   = (uint32_t)((lane >> 3) & 1);

    const int NCHUNK = D_ / 32;   // 32
    load_chunk(0, 0);
    load_chunk(1, 1);

    for (int i = 0; i < NCHUNK; i++) {
        if (i + 1 < NCHUNK) cp_wait1(); else cp_wait0();
        __syncthreads();
        if (i + 2 < NCHUNK) load_chunk((i + 2) % 3, i + 2);

        const uint32_t stg = sbase + (i % 3) * QSTAGE;
        const uint32_t Ab = stg;
        const uint32_t Bbh = stg + 1u * QBUF, Bbl = stg + 2u * QBUF;

#pragma unroll
        for (int kkb = 0; kkb < 2; kkb++) {
            const uint32_t acsw = (((uint32_t)(kkb * 2) + a_cu) ^ a_mask) << 4;
            const uint32_t bcsw = (((uint32_t)(kkb * 2) + b_cu) ^ b_mask) << 4;
            uint32_t a4[2][4];
            ldsm4(a4[0], Ab + (uint32_t)(a_rowb) * 64 + acsw);
            ldsm4(a4[1], Ab + (uint32_t)(a_rowb + 16) * 64 + acsw);
#pragma unroll
            for (int half = 0; half < 2; half++) {
                uint32_t bh4[2][4], bl4[2][4];
#pragma unroll
                for (int p = 0; p < 2; p++) {
                    const int np = half * 2 + p;
                    ldsm4(bh4[p], Bbh + (uint32_t)(b_rowb + np * 16) * 64 + bcsw);
                    ldsm4(bl4[p], Bbl + (uint32_t)(b_rowb + np * 16) * 64 + bcsw);
                }
#pragma unroll
                for (int mt = 0; mt < 2; mt++)
#pragma unroll
                    for (int q = 0; q < 4; q++) {
                        const int nt = half * 4 + q;
                        float* cc = c[mt][nt];
                        mma16816h(cc, a4[mt],
                                  bh4[q >> 1][(q & 1) * 2], bh4[q >> 1][(q & 1) * 2 + 1]);
                        mma16816h(cc, a4[mt],
                                  bl4[q >> 1][(q & 1) * 2], bl4[q >> 1][(q & 1) * 2 + 1]);
                    }
            }
        }
    }

    const int nb = n0 + wn * 64;
#pragma unroll
    for (int mt = 0; mt < 2; mt++) {
        const int r0 = m0 + wm * 32 + mt * 16 + (lane >> 2);
#pragma unroll
        for (int nt = 0; nt < 8; nt++) {
            const int ng = nb + nt * 8 + (lane & 3) * 2;
            const float bx = bias[ng], by = bias[ng + 1];
            const int h = ng >> 6;
            const int dd = ng & 63;
            const int bb0 = r0 >> 11, sI0 = r0 & (S_ - 1);
            const int r1 = r0 + 8;
            const int bb1 = r1 >> 11, sI1 = r1 & (S_ - 1);
            const size_t o0i = ((size_t)(bb0 * H_ + h) * S_ + sI0) * HD_ + dd;
            const size_t o1i = ((size_t)(bb1 * H_ + h) * S_ + sI1) * HD_ + dd;
            *(uint32_t*)&Ofp[o0i] =
                pack_f16((c[mt][nt][0] + bx) * scl, (c[mt][nt][1] + by) * scl);
            *(uint32_t*)&Ofp[o1i] =
                pack_f16((c[mt][nt][2] + bx) * scl, (c[mt][nt][3] + by) * scl);
        }
    }
}

// ---------------------------------------------------------------------------
// Output GEMM: single fp16 1-term. out[M,D] = att @ Wo^T + bo (fp32 out).
// ---------------------------------------------------------------------------
#define OBUF (128 * 64)
#define OSTAGE (2 * OBUF)
#define OGEMM_SMEM (3 * OSTAGE)   // 49152

__global__ __launch_bounds__(256, 2) void gemm_out_kernel(
    const __half* __restrict__ Af, const __half* __restrict__ Wof,
    const float* __restrict__ bias, float* __restrict__ out)
{
    extern __shared__ __align__(16) char smem[];
    const uint32_t sbase = smem_u32(smem);
    const int tid  = threadIdx.x;
    const int wid  = tid >> 5;
    const int lane = tid & 31;
    const int wm   = wid & 3;
    const int wn   = wid >> 2;
    const int n0 = blockIdx.x * 128;
    const int m0 = blockIdx.y * 128;

    float c[2][8][4];
#pragma unroll
    for (int i = 0; i < 2; i++)
#pragma unroll
        for (int j = 0; j < 8; j++)
#pragma unroll
            for (int q = 0; q < 4; q++) c[i][j][q] = 0.0f;

    auto load_chunk = [&](int stage, int kc) {
        const uint32_t sb = sbase + stage * OSTAGE;
#pragma unroll
        for (int u = 0; u < 2; u++) {
            const int idx = tid * 2 + u;
            const int r = idx >> 2;
            const int c4 = idx & 3;
            const uint32_t off = (uint32_t)(r * 64 + ((c4 ^ ((r >> 1) & 3)) << 4));
            cp16(sb +        off, Af  + (size_t)(m0 + r) * D_ + kc * 32 + c4 * 8);
            cp16(sb + OBUF + off, Wof + (size_t)(n0 + r) * D_ + kc * 32 + c4 * 8);
        }
        cp_commit();
    };

    const int a_rowb = wm * 32 + (lane & 15);
    const uint32_t a_mask = (uint32_t)(((lane & 15) >> 1) & 3);
    const uint32_t a_cu   = (uint32_t)(lane >> 4);
    const int b_rowb = wn * 64 + ((lane >> 4) & 1) * 8 + (lane & 7);
    const uint32_t b_mask = (uint32_t)(((lane & 7) >> 1) & 3);
    const uint32_t b_cu   = (uint32_t)((lane >> 3) & 1);

    const int NCHUNK = D_ / 32;
    load_chunk(0, 0);
    load_chunk(1, 1);

    for (int i = 0; i < NCHUNK; i++) {
        if (i + 1 < NCHUNK) cp_wait1(); else cp_wait0();
        __syncthreads();
        if (i + 2 < NCHUNK) load_chunk((i + 2) % 3, i + 2);

        const uint32_t stg = sbase + (i % 3) * OSTAGE;
        const uint32_t Ab = stg, Bb = stg + OBUF;

#pragma unroll
        for (int kkb = 0; kkb < 2; kkb++) {
            const uint32_t acsw = (((uint32_t)(kkb * 2) + a_cu) ^ a_mask) << 4;
            const uint32_t bcsw = (((uint32_t)(kkb * 2) + b_cu) ^ b_mask) << 4;
            uint32_t a4[2][4];
            ldsm4(a4[0], Ab + (uint32_t)(a_rowb) * 64 + acsw);
            ldsm4(a4[1], Ab + (uint32_t)(a_rowb + 16) * 64 + acsw);
#pragma unroll
            for (int half = 0; half < 2; half++) {
                uint32_t b4[2][4];
#pragma unroll
                for (int p = 0; p < 2; p++) {
                    const int np = half * 2 + p;
                    ldsm4(b4[p], Bb + (uint32_t)(b_rowb + np * 16) * 64 + bcsw);
                }
#pragma unroll
                for (int mt = 0; mt < 2; mt++)
#pragma unroll
                    for (int q = 0; q < 4; q++) {
                        const int nt = half * 4 + q;
                        mma16816h(c[mt][nt], a4[mt],
                                  b4[q >> 1][(q & 1) * 2], b4[q >> 1][(q & 1) * 2 + 1]);
                    }
            }
        }
    }

    const int nb = n0 + wn * 64;
#pragma unroll
    for (int mt = 0; mt < 2; mt++) {
        const int r0 = m0 + wm * 32 + mt * 16 + (lane >> 2);
#pragma unroll
        for (int nt = 0; nt < 8; nt++) {
            const int ng = nb + nt * 8 + (lane & 3) * 2;
            const float bx = bias[ng], by = bias[ng + 1];
            *(float2*)&out[(size_t)r0 * D_ + ng] =
                make_float2(c[mt][nt][0] + bx, c[mt][nt][1] + by);
            *(float2*)&out[(size_t)(r0 + 8) * D_ + ng] =
                make_float2(c[mt][nt][2] + bx, c[mt][nt][3] + by);
        }
    }
}

// ---------------------------------------------------------------------------
// Tensor-core flash attention (unchanged from R13: single fp16, 3-stage KV
// ring, f16x2 ex2 softmax, ones-mma l accumulation).
// ---------------------------------------------------------------------------
#define FL_QBUF 16384
#define FL_KVBUF 8192
#define FL_KVST (2 * FL_KVBUF)
#define FL_SMEM (FL_QBUF + 3 * FL_KVST)   // 64KB
#define ONES_F16X2 0x3C003C00u

__global__ __launch_bounds__(256) void flash_tc_kernel(
    const __half* __restrict__ Qf, const __half* __restrict__ Kf,
    const __half* __restrict__ Vf, __half* __restrict__ Af)
{
    extern __shared__ __align__(16) char smem[];
    const uint32_t base = smem_u32(smem);
    const int tid = threadIdx.x, wid = tid >> 5, lane = tid & 31;
    const int q0 = blockIdx.x * 128;
    const int bh = blockIdx.y;
    const size_t hb = (size_t)bh * S_ * HD_;

#pragma unroll
    for (int u = 0; u < 4; u++) {
        const int idx = tid + u * 256;
        const int r = idx >> 3;
        const int c = idx & 7;
        cp16(base + SWF(r, c), Qf + hb + (size_t)(q0 + r) * HD_ + c * 8);
    }
    cp_commit();

    auto loadkv = [&](int st, int kb) {
        const uint32_t sb = base + FL_QBUF + st * FL_KVST;
#pragma unroll
        for (int u = 0; u < 4; u++) {
            const int idx = tid + u * 256;
            const int b2 = idx >> 9;
            const int r = (idx >> 3) & 63;
            const int c = idx & 7;
            const __half* g = (b2 == 0) ? Kf : Vf;
            cp16(sb + b2 * FL_KVBUF + SWF(r, c),
                 g + hb + (size_t)(kb * 64 + r) * HD_ + c * 8);
        }
        cp_commit();
    };
    loadkv(0, 0);
    loadkv(1, 1);

    float o[8][4];
#pragma unroll
    for (int nt = 0; nt < 8; nt++)
#pragma unroll
        for (int q = 0; q < 4; q++) o[nt][q] = 0.0f;
    float ol[4] = {0.0f, 0.0f, 0.0f, 0.0f};
    float m0r = -1e30f, m1r = -1e30f;

    const int a_row = wid * 16 + (lane & 7) + ((lane >> 3) & 1) * 8;
    const int a_c   = lane >> 4;
    const int k_row = ((lane >> 4) & 1) * 8 + (lane & 7);
    const int k_c   = (lane >> 3) & 1;
    const int v_row = ((lane >> 3) & 1) * 8 + (lane & 7);
    const int v_c   = lane >> 4;

    const int NB = S_ / 64;   // 32
    for (int kb = 0; kb < NB; kb++) {
        if (kb < NB - 1) cp_wait1(); else cp_wait0();
        __syncthreads();
        if (kb + 2 < NB) loadkv((kb + 2) % 3, kb + 2);

        const uint32_t stg = base + FL_QBUF + (kb % 3) * FL_KVST;
        const uint32_t vbb = stg + FL_KVBUF;

        float s[8][4];
#pragma unroll
        for (int nt = 0; nt < 8; nt++)
#pragma unroll
            for (int q = 0; q < 4; q++) s[nt][q] = 0.0f;

#pragma unroll
        for (int ks = 0; ks < 4; ks++) {
            uint32_t a4[4];
            ldsm4(a4, base + SWF(a_row, 2 * ks + a_c));
#pragma unroll
            for (int np = 0; np < 4; np++) {
                uint32_t b4[4];
                ldsm4(b4, stg + SWF(np * 16 + k_row, 2 * ks + k_c));
                mma16816h(s[2 * np],     a4, b4[0], b4[1]);
                mma16816h(s[2 * np + 1], a4, b4[2], b4[3]);
            }
        }

        float mx0 = -1e30f, mx1 = -1e30f;
#pragma unroll
        for (int nt = 0; nt < 8; nt++) {
            mx0 = fmaxf(mx0, fmaxf(s[nt][0], s[nt][1]));
            mx1 = fmaxf(mx1, fmaxf(s[nt][2], s[nt][3]));
        }
        mx0 = fmaxf(mx0, __shfl_xor_sync(0xffffffffu, mx0, 1));
        mx0 = fmaxf(mx0, __shfl_xor_sync(0xffffffffu, mx0, 2));
        mx1 = fmaxf(mx1, __shfl_xor_sync(0xffffffffu, mx1, 1));
        mx1 = fmaxf(mx1, __shfl_xor_sync(0xffffffffu, mx1, 2));
        const float mn0 = fmaxf(m0r, mx0);
        const float mn1 = fmaxf(m1r, mx1);
        const float al0 = ex2f(m0r - mn0);
        const float al1 = ex2f(m1r - mn1);
        m0r = mn0; m1r = mn1;

#pragma unroll
        for (int nt = 0; nt < 8; nt++) {
            o[nt][0] *= al0; o[nt][1] *= al0;
            o[nt][2] *= al1; o[nt][3] *= al1;
        }
        ol[0] *= al0; ol[1] *= al0;
        ol[2] *= al1; ol[3] *= al1;

        uint32_t ap[4][4];
#pragma unroll
        for (int kc = 0; kc < 4; kc++) {
            ap[kc][0] = ex2_pack(s[2 * kc][0] - mn0,     s[2 * kc][1] - mn0);
            ap[kc][1] = ex2_pack(s[2 * kc][2] - mn1,     s[2 * kc][3] - mn1);
            ap[kc][2] = ex2_pack(s[2 * kc + 1][0] - mn0, s[2 * kc + 1][1] - mn0);
            ap[kc][3] = ex2_pack(s[2 * kc + 1][2] - mn1, s[2 * kc + 1][3] - mn1);
        }

#pragma unroll
        for (int kc = 0; kc < 4; kc++)
            mma16816h(ol, ap[kc], ONES_F16X2, ONES_F16X2);

#pragma unroll
        for (int dp = 0; dp < 4; dp++) {
#pragma unroll
            for (int kc = 0; kc < 4; kc++) {
                uint32_t v4[4];
                ldsm4t(v4, vbb + SWF(kc * 16 + v_row, 2 * dp + v_c));
                mma16816h(o[2 * dp],     ap[kc], v4[0], v4[1]);
                mma16816h(o[2 * dp + 1], ap[kc], v4[2], v4[3]);
            }
        }
    }

    const float inv0 = 1.0f / ol[0];
    const float inv1 = 1.0f / ol[2];
    const int h = bh & (H_ - 1);
    const int bb = bh >> 4;
    const int r0 = q0 + wid * 16 + (lane >> 2);
    const int r1 = r0 + 8;
#pragma unroll
    for (int nt = 0; nt < 8; nt++) {
        const int gd = h * 64 + nt * 8 + (lane & 3) * 2;
        const size_t i0 = ((size_t)bb * S_ + r0) * D_ + gd;
        const size_t i1 = ((size_t)bb * S_ + r1) * D_ + gd;
        *(uint32_t*)&Af[i0] = pack_f16(o[nt][0] * inv0, o[nt][1] * inv0);
        *(uint32_t*)&Af[i1] = pack_f16(o[nt][2] * inv1, o[nt][3] * inv1);
    }
}

// ---------------------------------------------------------------------------

extern "C" void kernel_launch(void* const* d_in, const int* in_sizes, int n_in,
                              void* d_out, int out_size)
{
    (void)in_sizes; (void)n_in; (void)out_size;
    const float* x  = (const float*)d_in[0];
    const float* Wq = (const float*)d_in[1];
    const float* bq = (const float*)d_in[2];
    const float* Wk = (const float*)d_in[3];
    const float* bk = (const float*)d_in[4];
    const float* Wv = (const float*)d_in[5];
    const float* bv = (const float*)d_in[6];
    const float* Wo = (const float*)d_in[7];
    const float* bo = (const float*)d_in[8];
    float* out = (float*)d_out;

    __half *xf, *wqh, *wql, *wof, *qf, *kf, *vf, *af;
    cudaGetSymbolAddress((void**)&xf,  g_xf);
    cudaGetSymbolAddress((void**)&wqh, g_wqh);
    cudaGetSymbolAddress((void**)&wql, g_wql);
    cudaGetSymbolAddress((void**)&wof, g_wof);
    cudaGetSymbolAddress((void**)&qf,  g_qf);
    cudaGetSymbolAddress((void**)&kf,  g_kf);
    cudaGetSymbolAddress((void**)&vf,  g_vf);
    cudaGetSymbolAddress((void**)&af,  g_af);

    cudaFuncSetAttribute(gemm_qkv_kernel,
        cudaFuncAttributeMaxDynamicSharedMemorySize, QGEMM_SMEM);
    cudaFuncSetAttribute(gemm_out_kernel,
        cudaFuncAttributeMaxDynamicSharedMemorySize, OGEMM_SMEM);
    cudaFuncSetAttribute(flash_tc_kernel,
        cudaFuncAttributeMaxDynamicSharedMemorySize, FL_SMEM);

    const int NEL = M_ * D_;
    cvt_kernel<<<NEL / 4096, 256>>>(x, xf, NEL);
    transW_kernel<<<dim3(16, 32, 4), 256>>>(Wq, Wk, Wv, Wo, wqh, wql, wof);

    gemm_qkv_kernel<<<dim3(8, 32, 3), 256, QGEMM_SMEM>>>(
        xf, wqh, wql, bq, bk, bv, qf, kf, vf);

    flash_tc_kernel<<<dim3(S_ / 128, B_ * H_), 256, FL_SMEM>>>(qf, kf, vf, af);

    gemm_out_kernel<<<dim3(8, 32), 256, OGEMM_SMEM>>>(af, wof, bo, out);
}

// round 16
// speedup vs baseline: 2.2782x; 1.2673x over previous
#include <cuda_runtime.h>
#include <cuda_bf16.h>
#include <cuda_fp16.h>
#include <math.h>
#include <stdint.h>

#define B_ 2
#define S_ 2048
#define D_ 1024
#define H_ 16
#define HD_ 64
#define M_ 4096

// ---------------- scratch (__device__ globals; allocation-free rule) -------
__device__ __half g_xf[M_ * D_];                // x as single fp16
__device__ __half g_wf[4 * D_ * D_];            // Wq/Wk/Wv/Wo ^T [n][k], fp16
__device__ __half g_qf[M_ * D_];                // Q/K/V single fp16, [B,H,S,HD]
__device__ __half g_kf[M_ * D_];
__device__ __half g_vf[M_ * D_];
__device__ __half g_af[M_ * D_];                // attended, fp16 [B,S,D]

// ---------------- helpers ---------------------------------------------------
__device__ __forceinline__ uint32_t smem_u32(const void* p) {
    uint32_t a;
    asm("{ .reg .u64 t; cvta.to.shared.u64 t, %1; cvt.u32.u64 %0, t; }"
        : "=r"(a) : "l"(p));
    return a;
}
__device__ __forceinline__ void cp16(uint32_t dst, const void* src) {
    asm volatile("cp.async.cg.shared.global [%0], [%1], 16;" :: "r"(dst), "l"(src));
}
__device__ __forceinline__ void cp_commit() {
    asm volatile("cp.async.commit_group;" ::: "memory");
}
__device__ __forceinline__ void cp_wait1() {
    asm volatile("cp.async.wait_group 1;" ::: "memory");
}
__device__ __forceinline__ void cp_wait0() {
    asm volatile("cp.async.wait_group 0;" ::: "memory");
}
__device__ __forceinline__ void ldsm4(uint32_t* r, uint32_t addr) {
    asm volatile("ldmatrix.sync.aligned.m8n8.x4.shared.b16 {%0,%1,%2,%3}, [%4];"
                 : "=r"(r[0]), "=r"(r[1]), "=r"(r[2]), "=r"(r[3]) : "r"(addr));
}
__device__ __forceinline__ void ldsm4t(uint32_t* r, uint32_t addr) {
    asm volatile("ldmatrix.sync.aligned.m8n8.x4.trans.shared.b16 {%0,%1,%2,%3}, [%4];"
                 : "=r"(r[0]), "=r"(r[1]), "=r"(r[2]), "=r"(r[3]) : "r"(addr));
}
__device__ __forceinline__ void mma16816h(float* c, const uint32_t* a,
                                          uint32_t b0, uint32_t b1) {
    asm volatile(
        "mma.sync.aligned.m16n8k16.row.col.f32.f16.f16.f32 "
        "{%0,%1,%2,%3}, {%4,%5,%6,%7}, {%8,%9}, {%0,%1,%2,%3};"
        : "+f"(c[0]), "+f"(c[1]), "+f"(c[2]), "+f"(c[3])
        : "r"(a[0]), "r"(a[1]), "r"(a[2]), "r"(a[3]), "r"(b0), "r"(b1));
}
__device__ __forceinline__ float ex2f(float x) {
    float r;
    asm("ex2.approx.ftz.f32 %0, %1;" : "=f"(r) : "f"(x));
    return r;
}
// Pack two fp32 exponent args to fp16x2 and exponentiate
__device__ __forceinline__ uint32_t ex2_pack(float a_lo, float a_hi) {
    uint32_t h;
    asm("{ .reg .b32 t;\n\t"
        "cvt.rn.f16x2.f32 t, %2, %1;\n\t"
        "ex2.approx.f16x2 t, t;\n\t"
        "mov.b32 %0, t; }"
        : "=r"(h) : "f"(a_lo), "f"(a_hi));
    return h;
}
// XOR swizzle for 128B rows (flash): 8 x 16B units
#define SWF(r, c) ((uint32_t)((r) * 128 + ((((c) ^ ((r) & 7))) << 4)))

__device__ __forceinline__ uint32_t pack_f16(float x, float y) {
    __half2 p = __floats2half2_rn(x, y);
    return *(uint32_t*)&p;
}

// ---------------------------------------------------------------------------
// Conversion kernels
// ---------------------------------------------------------------------------
__global__ void cvt_kernel(const float* __restrict__ src,
                           __half* __restrict__ dst, int n)
{
    const int base = blockIdx.x * 4096 + threadIdx.x * 4;
#pragma unroll
    for (int p = 0; p < 4; p++) {
        const int i = base + p * 1024;
        if (i >= n) return;
        float4 v = *(const float4*)(src + i);
        *(uint32_t*)(dst + i)     = pack_f16(v.x, v.y);
        *(uint32_t*)(dst + i + 2) = pack_f16(v.z, v.w);
    }
}

// W [k][n] fp32 -> W^T [n][k] fp16 single. 32k x 64n tiles, 256 threads.
__global__ void transW_kernel(const float* __restrict__ W0, const float* __restrict__ W1,
                              const float* __restrict__ W2, const float* __restrict__ W3,
                              __half* __restrict__ wf)
{
    __shared__ float t[32][65];
    const int z = blockIdx.z;
    const float* W = (z == 0) ? W0 : (z == 1) ? W1 : (z == 2) ? W2 : W3;
    const int n0 = blockIdx.x * 64, k0 = blockIdx.y * 32;
    const int tid = threadIdx.x;
#pragma unroll
    for (int p = 0; p < 8; p++) {
        const int lin = tid + p * 256;
        const int r = lin >> 6, c = lin & 63;
        t[r][c] = W[(size_t)(k0 + r) * D_ + n0 + c];
    }
    __syncthreads();
    __half* Of = wf + (size_t)z * D_ * D_;
    const int n = n0 + (tid >> 2);
    const int kb = (tid & 3) * 8;
    uint32_t fv[4];
#pragma unroll
    for (int j = 0; j < 4; j++)
        fv[j] = pack_f16(t[kb + 2 * j][tid >> 2], t[kb + 2 * j + 1][tid >> 2]);
    *(uint4*)&Of[(size_t)n * D_ + k0 + kb] = *(uint4*)fv;
}

// ---------------------------------------------------------------------------
// Single-fp16 1-term GEMM, CTA 128x128, BK=32, 3-stage pipeline.
// SCATTER=1 (QKV): z selects weight/bias/out, fp16 head-scattered output,
//                  Q (z==0) pre-scaled by 0.125*log2(e).
// SCATTER=0 (O):   fp32 row-major output.
// ---------------------------------------------------------------------------
#define GBUF (128 * 64)
#define GSTAGE (2 * GBUF)          // A + W = 16KB
#define GEMM_SMEM (3 * GSTAGE)     // 49152
#define LOG2E 1.4426950408889634f

template <int SCATTER>
__global__ __launch_bounds__(256, 2) void gemm_h1_kernel(
    const __half* __restrict__ Af, const __half* __restrict__ Wf,
    const float* __restrict__ b0p, const float* __restrict__ b1p,
    const float* __restrict__ b2p,
    float* __restrict__ fo,
    __half* __restrict__ of0, __half* __restrict__ of1, __half* __restrict__ of2)
{
    extern __shared__ __align__(16) char smem[];
    const uint32_t sbase = smem_u32(smem);
    const int tid  = threadIdx.x;
    const int wid  = tid >> 5;
    const int lane = tid & 31;
    const int wm   = wid & 3;
    const int wn   = wid >> 2;
    const int n0 = blockIdx.x * 128;
    const int m0 = blockIdx.y * 128;
    const int z  = blockIdx.z;

    const __half* Bf = Wf + (size_t)z * D_ * D_;
    const float* bias = (z == 0) ? b0p : (z == 1) ? b1p : b2p;
    __half* Ofp = (z == 0) ? of0 : (z == 1) ? of1 : of2;
    const float scl = (SCATTER && z == 0) ? (0.125f * LOG2E) : 1.0f;

    float c[2][8][4];
#pragma unroll
    for (int i = 0; i < 2; i++)
#pragma unroll
        for (int j = 0; j < 8; j++)
#pragma unroll
            for (int q = 0; q < 4; q++) c[i][j][q] = 0.0f;

    auto load_chunk = [&](int stage, int kc) {
        const uint32_t sb = sbase + stage * GSTAGE;
#pragma unroll
        for (int u = 0; u < 2; u++) {
            const int idx = tid * 2 + u;
            const int r = idx >> 2;
            const int c4 = idx & 3;
            const uint32_t off = (uint32_t)(r * 64 + ((c4 ^ ((r >> 1) & 3)) << 4));
            cp16(sb +        off, Af + (size_t)(m0 + r) * D_ + kc * 32 + c4 * 8);
            cp16(sb + GBUF + off, Bf + (size_t)(n0 + r) * D_ + kc * 32 + c4 * 8);
        }
        cp_commit();
    };

    const int a_rowb = wm * 32 + (lane & 15);
    const uint32_t a_mask = (uint32_t)(((lane & 15) >> 1) & 3);
    const uint32_t a_cu   = (uint32_t)(lane >> 4);
    const int b_rowb = wn * 64 + ((lane >> 4) & 1) * 8 + (lane & 7);
    const uint32_t b_mask = (uint32_t)(((lane & 7) >> 1) & 3);
    const uint32_t b_cu   = (uint32_t)((lane >> 3) & 1);

    const int NCHUNK = D_ / 32;   // 32
    load_chunk(0, 0);
    load_chunk(1, 1);

    for (int i = 0; i < NCHUNK; i++) {
        if (i + 1 < NCHUNK) cp_wait1(); else cp_wait0();
        __syncthreads();
        if (i + 2 < NCHUNK) load_chunk((i + 2) % 3, i + 2);

        const uint32_t stg = sbase + (i % 3) * GSTAGE;
        const uint32_t Ab = stg, Bb = stg + GBUF;

#pragma unroll
        for (int kkb = 0; kkb < 2; kkb++) {
            const uint32_t acsw = (((uint32_t)(kkb * 2) + a_cu) ^ a_mask) << 4;
            const uint32_t bcsw = (((uint32_t)(kkb * 2) + b_cu) ^ b_mask) << 4;
            uint32_t a4[2][4];
            ldsm4(a4[0], Ab + (uint32_t)(a_rowb) * 64 + acsw);
            ldsm4(a4[1], Ab + (uint32_t)(a_rowb + 16) * 64 + acsw);
#pragma unroll
            for (int half = 0; half < 2; half++) {
                uint32_t b4[2][4];
#pragma unroll
                for (int p = 0; p < 2; p++) {
                    const int np = half * 2 + p;
                    ldsm4(b4[p], Bb + (uint32_t)(b_rowb + np * 16) * 64 + bcsw);
                }
#pragma unroll
                for (int mt = 0; mt < 2; mt++)
#pragma unroll
                    for (int q = 0; q < 4; q++) {
                        const int nt = half * 4 + q;
                        mma16816h(c[mt][nt], a4[mt],
                                  b4[q >> 1][(q & 1) * 2], b4[q >> 1][(q & 1) * 2 + 1]);
                    }
            }
        }
    }

    const int nb = n0 + wn * 64;
#pragma unroll
    for (int mt = 0; mt < 2; mt++) {
        const int r0 = m0 + wm * 32 + mt * 16 + (lane >> 2);
#pragma unroll
        for (int nt = 0; nt < 8; nt++) {
            const int ng = nb + nt * 8 + (lane & 3) * 2;
            const float bx = bias[ng], by = bias[ng + 1];
            if (SCATTER) {
                const int h = ng >> 6;
                const int dd = ng & 63;
                const int bb0 = r0 >> 11, sI0 = r0 & (S_ - 1);
                const int r1 = r0 + 8;
                const int bb1 = r1 >> 11, sI1 = r1 & (S_ - 1);
                const size_t o0i = ((size_t)(bb0 * H_ + h) * S_ + sI0) * HD_ + dd;
                const size_t o1i = ((size_t)(bb1 * H_ + h) * S_ + sI1) * HD_ + dd;
                *(uint32_t*)&Ofp[o0i] =
                    pack_f16((c[mt][nt][0] + bx) * scl, (c[mt][nt][1] + by) * scl);
                *(uint32_t*)&Ofp[o1i] =
                    pack_f16((c[mt][nt][2] + bx) * scl, (c[mt][nt][3] + by) * scl);
            } else {
                *(float2*)&fo[(size_t)r0 * D_ + ng] =
                    make_float2(c[mt][nt][0] + bx, c[mt][nt][1] + by);
                *(float2*)&fo[(size_t)(r0 + 8) * D_ + ng] =
                    make_float2(c[mt][nt][2] + bx, c[mt][nt][3] + by);
            }
        }
    }
}

// ---------------------------------------------------------------------------
// Tensor-core flash attention (R13 shape: single fp16, 3-stage KV ring,
// f16x2 ex2 softmax, ones-mma l accumulation).
// ---------------------------------------------------------------------------
#define FL_QBUF 16384
#define FL_KVBUF 8192
#define FL_KVST (2 * FL_KVBUF)
#define FL_SMEM (FL_QBUF + 3 * FL_KVST)   // 64KB
#define ONES_F16X2 0x3C003C00u

__global__ __launch_bounds__(256) void flash_tc_kernel(
    const __half* __restrict__ Qf, const __half* __restrict__ Kf,
    const __half* __restrict__ Vf, __half* __restrict__ Af)
{
    extern __shared__ __align__(16) char smem[];
    const uint32_t base = smem_u32(smem);
    const int tid = threadIdx.x, wid = tid >> 5, lane = tid & 31;
    const int q0 = blockIdx.x * 128;
    const int bh = blockIdx.y;
    const size_t hb = (size_t)bh * S_ * HD_;

#pragma unroll
    for (int u = 0; u < 4; u++) {
        const int idx = tid + u * 256;
        const int r = idx >> 3;
        const int c = idx & 7;
        cp16(base + SWF(r, c), Qf + hb + (size_t)(q0 + r) * HD_ + c * 8);
    }
    cp_commit();

    auto loadkv = [&](int st, int kb) {
        const uint32_t sb = base + FL_QBUF + st * FL_KVST;
#pragma unroll
        for (int u = 0; u < 4; u++) {
            const int idx = tid + u * 256;
            const int b2 = idx >> 9;
            const int r = (idx >> 3) & 63;
            const int c = idx & 7;
            const __half* g = (b2 == 0) ? Kf : Vf;
            cp16(sb + b2 * FL_KVBUF + SWF(r, c),
                 g + hb + (size_t)(kb * 64 + r) * HD_ + c * 8);
        }
        cp_commit();
    };
    loadkv(0, 0);
    loadkv(1, 1);

    float o[8][4];
#pragma unroll
    for (int nt = 0; nt < 8; nt++)
#pragma unroll
        for (int q = 0; q < 4; q++) o[nt][q] = 0.0f;
    float ol[4] = {0.0f, 0.0f, 0.0f, 0.0f};
    float m0r = -1e30f, m1r = -1e30f;

    const int a_row = wid * 16 + (lane & 7) + ((lane >> 3) & 1) * 8;
    const int a_c   = lane >> 4;
    const int k_row = ((lane >> 4) & 1) * 8 + (lane & 7);
    const int k_c   = (lane >> 3) & 1;
    const int v_row = ((lane >> 3) & 1) * 8 + (lane & 7);
    const int v_c   = lane >> 4;

    const int NB = S_ / 64;   // 32
    for (int kb = 0; kb < NB; kb++) {
        if (kb < NB - 1) cp_wait1(); else cp_wait0();
        __syncthreads();
        if (kb + 2 < NB) loadkv((kb + 2) % 3, kb + 2);

        const uint32_t stg = base + FL_QBUF + (kb % 3) * FL_KVST;
        const uint32_t vbb = stg + FL_KVBUF;

        float s[8][4];
#pragma unroll
        for (int nt = 0; nt < 8; nt++)
#pragma unroll
            for (int q = 0; q < 4; q++) s[nt][q] = 0.0f;

#pragma unroll
        for (int ks = 0; ks < 4; ks++) {
            uint32_t a4[4];
            ldsm4(a4, base + SWF(a_row, 2 * ks + a_c));
#pragma unroll
            for (int np = 0; np < 4; np++) {
                uint32_t b4[4];
                ldsm4(b4, stg + SWF(np * 16 + k_row, 2 * ks + k_c));
                mma16816h(s[2 * np],     a4, b4[0], b4[1]);
                mma16816h(s[2 * np + 1], a4, b4[2], b4[3]);
            }
        }

        float mx0 = -1e30f, mx1 = -1e30f;
#pragma unroll
        for (int nt = 0; nt < 8; nt++) {
            mx0 = fmaxf(mx0, fmaxf(s[nt][0], s[nt][1]));
            mx1 = fmaxf(mx1, fmaxf(s[nt][2], s[nt][3]));
        }
        mx0 = fmaxf(mx0, __shfl_xor_sync(0xffffffffu, mx0, 1));
        mx0 = fmaxf(mx0, __shfl_xor_sync(0xffffffffu, mx0, 2));
        mx1 = fmaxf(mx1, __shfl_xor_sync(0xffffffffu, mx1, 1));
        mx1 = fmaxf(mx1, __shfl_xor_sync(0xffffffffu, mx1, 2));
        const float mn0 = fmaxf(m0r, mx0);
        const float mn1 = fmaxf(m1r, mx1);
        const float al0 = ex2f(m0r - mn0);
        const float al1 = ex2f(m1r - mn1);
        m0r = mn0; m1r = mn1;

#pragma unroll
        for (int nt = 0; nt < 8; nt++) {
            o[nt][0] *= al0; o[nt][1] *= al0;
            o[nt][2] *= al1; o[nt][3] *= al1;
        }
        ol[0] *= al0; ol[1] *= al0;
        ol[2] *= al1; ol[3] *= al1;

        uint32_t ap[4][4];
#pragma unroll
        for (int kc = 0; kc < 4; kc++) {
            ap[kc][0] = ex2_pack(s[2 * kc][0] - mn0,     s[2 * kc][1] - mn0);
            ap[kc][1] = ex2_pack(s[2 * kc][2] - mn1,     s[2 * kc][3] - mn1);
            ap[kc][2] = ex2_pack(s[2 * kc + 1][0] - mn0, s[2 * kc + 1][1] - mn0);
            ap[kc][3] = ex2_pack(s[2 * kc + 1][2] - mn1, s[2 * kc + 1][3] - mn1);
        }

#pragma unroll
        for (int kc = 0; kc < 4; kc++)
            mma16816h(ol, ap[kc], ONES_F16X2, ONES_F16X2);

#pragma unroll
        for (int dp = 0; dp < 4; dp++) {
#pragma unroll
            for (int kc = 0; kc < 4; kc++) {
                uint32_t v4[4];
                ldsm4t(v4, vbb + SWF(kc * 16 + v_row, 2 * dp + v_c));
                mma16816h(o[2 * dp],     ap[kc], v4[0], v4[1]);
                mma16816h(o[2 * dp + 1], ap[kc], v4[2], v4[3]);
            }
        }
    }

    const float inv0 = 1.0f / ol[0];
    const float inv1 = 1.0f / ol[2];
    const int h = bh & (H_ - 1);
    const int bb = bh >> 4;
    const int r0 = q0 + wid * 16 + (lane >> 2);
    const int r1 = r0 + 8;
#pragma unroll
    for (int nt = 0; nt < 8; nt++) {
        const int gd = h * 64 + nt * 8 + (lane & 3) * 2;
        const size_t i0 = ((size_t)bb * S_ + r0) * D_ + gd;
        const size_t i1 = ((size_t)bb * S_ + r1) * D_ + gd;
        *(uint32_t*)&Af[i0] = pack_f16(o[nt][0] * inv0, o[nt][1] * inv0);
        *(uint32_t*)&Af[i1] = pack_f16(o[nt][2] * inv1, o[nt][3] * inv1);
    }
}

// ---------------------------------------------------------------------------

extern "C" void kernel_launch(void* const* d_in, const int* in_sizes, int n_in,
                              void* d_out, int out_size)
{
    (void)in_sizes; (void)n_in; (void)out_size;
    const float* x  = (const float*)d_in[0];
    const float* Wq = (const float*)d_in[1];
    const float* bq = (const float*)d_in[2];
    const float* Wk = (const float*)d_in[3];
    const float* bk = (const float*)d_in[4];
    const float* Wv = (const float*)d_in[5];
    const float* bv = (const float*)d_in[6];
    const float* Wo = (const float*)d_in[7];
    const float* bo = (const float*)d_in[8];
    float* out = (float*)d_out;

    __half *xf, *wf, *qf, *kf, *vf, *af;
    cudaGetSymbolAddress((void**)&xf, g_xf);
    cudaGetSymbolAddress((void**)&wf, g_wf);
    cudaGetSymbolAddress((void**)&qf, g_qf);
    cudaGetSymbolAddress((void**)&kf, g_kf);
    cudaGetSymbolAddress((void**)&vf, g_vf);
    cudaGetSymbolAddress((void**)&af, g_af);

    cudaFuncSetAttribute(gemm_h1_kernel<1>,
        cudaFuncAttributeMaxDynamicSharedMemorySize, GEMM_SMEM);
    cudaFuncSetAttribute(gemm_h1_kernel<0>,
        cudaFuncAttributeMaxDynamicSharedMemorySize, GEMM_SMEM);
    cudaFuncSetAttribute(flash_tc_kernel,
        cudaFuncAttributeMaxDynamicSharedMemorySize, FL_SMEM);

    const int NEL = M_ * D_;
    cvt_kernel<<<NEL / 4096, 256>>>(x, xf, NEL);
    transW_kernel<<<dim3(16, 32, 4), 256>>>(Wq, Wk, Wv, Wo, wf);

    gemm_h1_kernel<1><<<dim3(8, 32, 3), 256, GEMM_SMEM>>>(
        xf, wf, bq, bk, bv, nullptr, qf, kf, vf);

    flash_tc_kernel<<<dim3(S_ / 128, B_ * H_), 256, FL_SMEM>>>(qf, kf, vf, af);

    gemm_h1_kernel<0><<<dim3(8, 32, 1), 256, GEMM_SMEM>>>(
        af, wf + (size_t)3 * D_ * D_, bo, bo, bo, out, nullptr, nullptr, nullptr);
}